// round 2
// baseline (speedup 1.0000x reference)
#include <cuda_runtime.h>
#include <math.h>

#define D_MODEL 1024
#define D_HEAD  64
#define BATCH   4
#define SEQ     4096
#define M_TOTAL (BATCH * SEQ)   // 16384

// Scratch for projected Q, K, V (device globals: no runtime allocation allowed)
__device__ float g_Q[M_TOTAL * D_HEAD];
__device__ float g_K[M_TOTAL * D_HEAD];
__device__ float g_V[M_TOTAL * D_HEAD];

// ---------------------------------------------------------------------------
// Projection kernel: out[m, h] = sum_k x[m, k] * W[k, h] + b[h]
// Tile: 64 rows x 64 cols (full head dim), BK = 32.
// 256 threads, each computes a 4x4 microtile.
// grid = (M_TOTAL/64, 3)  — y selects Q / K / V.
// ---------------------------------------------------------------------------
__global__ __launch_bounds__(256) void proj_kernel(
    const float* __restrict__ x,
    const float* __restrict__ Wq, const float* __restrict__ bq,
    const float* __restrict__ Wk, const float* __restrict__ bk,
    const float* __restrict__ Wv, const float* __restrict__ bv)
{
    const float* W;
    const float* bias;
    float* out;
    if (blockIdx.y == 0)      { W = Wq; bias = bq; out = g_Q; }
    else if (blockIdx.y == 1) { W = Wk; bias = bk; out = g_K; }
    else                      { W = Wv; bias = bv; out = g_V; }

    __shared__ float Xs[64][36];   // pad 36 (16B-aligned rows, conflict-free use)
    __shared__ float Ws[32][64];

    const int tid  = threadIdx.x;
    const int row0 = blockIdx.x * 64;
    const int tr   = tid >> 4;     // 0..15
    const int tc   = tid & 15;     // 0..15

    float acc[4][4] = {};

    for (int k0 = 0; k0 < D_MODEL; k0 += 32) {
        // Load X tile: 64 x 32 floats = 512 float4, 2 per thread
        #pragma unroll
        for (int i = 0; i < 2; i++) {
            int f = tid + i * 256;
            int m = f >> 3, c = f & 7;
            float4 v = *(const float4*)&x[(size_t)(row0 + m) * D_MODEL + k0 + c * 4];
            *(float4*)&Xs[m][c * 4] = v;
        }
        // Load W tile: 32 x 64 floats = 512 float4, 2 per thread
        #pragma unroll
        for (int i = 0; i < 2; i++) {
            int f = tid + i * 256;
            int kk = f >> 4, c = f & 15;
            float4 v = *(const float4*)&W[(size_t)(k0 + kk) * D_HEAD + c * 4];
            *(float4*)&Ws[kk][c * 4] = v;
        }
        __syncthreads();

        #pragma unroll
        for (int kk = 0; kk < 32; kk++) {
            float a[4], b[4];
            #pragma unroll
            for (int i = 0; i < 4; i++) a[i] = Xs[tr * 4 + i][kk];
            #pragma unroll
            for (int j = 0; j < 4; j++) b[j] = Ws[kk][tc * 4 + j];
            #pragma unroll
            for (int i = 0; i < 4; i++)
                #pragma unroll
                for (int j = 0; j < 4; j++)
                    acc[i][j] += a[i] * b[j];
        }
        __syncthreads();
    }

    #pragma unroll
    for (int i = 0; i < 4; i++) {
        const int r = row0 + tr * 4 + i;
        #pragma unroll
        for (int j = 0; j < 4; j++) {
            const int h = tc * 4 + j;
            out[(size_t)r * D_HEAD + h] = acc[i][j] + bias[h];
        }
    }
}

// ---------------------------------------------------------------------------
// Flash attention (fp32, online softmax).
// One block = one (batch, 64-row q-tile). 256 threads, 4x4 microtiles.
// Iterates causal k-tiles. K staged transposed (Kt[h][n]) so both GEMM inner
// loops read smem conflict-free. P staged through smem for the PV GEMM.
// grid = (64, BATCH); qb = 63 - blockIdx.x so heaviest tiles launch first.
// ---------------------------------------------------------------------------
#define SPAD 68   // 64 + 4 pad, keeps rows 16B-aligned

__global__ __launch_bounds__(256) void attn_kernel(float* __restrict__ out)
{
    extern __shared__ float sm[];
    float (*Qs)[SPAD] = (float(*)[SPAD])(sm);
    float (*Kt)[SPAD] = (float(*)[SPAD])(sm + 64 * SPAD);      // [h][n]
    float (*Vs)[SPAD] = (float(*)[SPAD])(sm + 2 * 64 * SPAD);  // [n][h]
    float (*Ps)[SPAD] = (float(*)[SPAD])(sm + 3 * 64 * SPAD);  // [q][n]

    const int qb = 63 - blockIdx.x;        // heaviest first
    const int b  = blockIdx.y;
    const float scale = 0.125f;            // 1/sqrt(64)

    const float* Q = g_Q + (size_t)b * SEQ * D_HEAD;
    const float* K = g_K + (size_t)b * SEQ * D_HEAD;
    const float* V = g_V + (size_t)b * SEQ * D_HEAD;

    const int tid = threadIdx.x;
    const int tr  = tid >> 4;              // row group 0..15
    const int tc  = tid & 15;              // col group 0..15

    // Load Q tile (64x64): 1024 float4, 4 per thread
    #pragma unroll
    for (int i = 0; i < 4; i++) {
        int f = tid + i * 256;
        int m = f >> 4, c = f & 15;
        float4 v = *(const float4*)&Q[(size_t)(qb * 64 + m) * D_HEAD + c * 4];
        *(float4*)&Qs[m][c * 4] = v;
    }

    float m_i[4], l_i[4];
    float acc[4][4] = {};
    #pragma unroll
    for (int i = 0; i < 4; i++) { m_i[i] = -INFINITY; l_i[i] = 0.0f; }

    for (int kb = 0; kb <= qb; kb++) {
        const float* Kp = K + (size_t)kb * 64 * D_HEAD;
        const float* Vp = V + (size_t)kb * 64 * D_HEAD;

        // Load K tile transposed -> Kt[h][n], and V tile natural -> Vs[n][h]
        #pragma unroll
        for (int i = 0; i < 4; i++) {
            int f = tid + i * 256;
            int n = f >> 4, c = f & 15;
            float4 kv = *(const float4*)&Kp[(size_t)n * D_HEAD + c * 4];
            Kt[c * 4 + 0][n] = kv.x;
            Kt[c * 4 + 1][n] = kv.y;
            Kt[c * 4 + 2][n] = kv.z;
            Kt[c * 4 + 3][n] = kv.w;
            float4 vv = *(const float4*)&Vp[(size_t)n * D_HEAD + c * 4];
            *(float4*)&Vs[n][c * 4] = vv;
        }
        __syncthreads();   // (also covers Qs on first iteration)

        // S = scale * Q K^T  (4x4 per thread)
        float s[4][4] = {};
        #pragma unroll
        for (int h = 0; h < 64; h++) {
            float a[4], bb[4];
            #pragma unroll
            for (int i = 0; i < 4; i++) a[i] = Qs[tr * 4 + i][h];
            #pragma unroll
            for (int j = 0; j < 4; j++) bb[j] = Kt[h][tc * 4 + j];
            #pragma unroll
            for (int i = 0; i < 4; i++)
                #pragma unroll
                for (int j = 0; j < 4; j++)
                    s[i][j] += a[i] * bb[j];
        }

        // Scale + causal mask (only the diagonal tile needs masking)
        if (kb == qb) {
            #pragma unroll
            for (int i = 0; i < 4; i++)
                #pragma unroll
                for (int j = 0; j < 4; j++) {
                    int qi = tr * 4 + i, ki = tc * 4 + j;
                    s[i][j] = (ki > qi) ? -INFINITY : s[i][j] * scale;
                }
        } else {
            #pragma unroll
            for (int i = 0; i < 4; i++)
                #pragma unroll
                for (int j = 0; j < 4; j++)
                    s[i][j] *= scale;
        }

        // Online softmax. Row stats reduced across the 16 threads sharing a row
        // (they are a 16-lane aligned group within a warp).
        float corr[4];
        #pragma unroll
        for (int i = 0; i < 4; i++) {
            float mx = fmaxf(fmaxf(s[i][0], s[i][1]), fmaxf(s[i][2], s[i][3]));
            #pragma unroll
            for (int off = 8; off >= 1; off >>= 1)
                mx = fmaxf(mx, __shfl_xor_sync(0xffffffffu, mx, off));
            float m_new = fmaxf(m_i[i], mx);
            corr[i] = __expf(m_i[i] - m_new);
            float rs = 0.0f;
            #pragma unroll
            for (int j = 0; j < 4; j++) {
                s[i][j] = __expf(s[i][j] - m_new);   // now P
                rs += s[i][j];
            }
            #pragma unroll
            for (int off = 8; off >= 1; off >>= 1)
                rs += __shfl_xor_sync(0xffffffffu, rs, off);
            l_i[i] = l_i[i] * corr[i] + rs;
            m_i[i] = m_new;
        }

        // Rescale O accumulator, stage P to smem
        #pragma unroll
        for (int i = 0; i < 4; i++)
            #pragma unroll
            for (int j = 0; j < 4; j++) {
                acc[i][j] *= corr[i];
                Ps[tr * 4 + i][tc * 4 + j] = s[i][j];
            }
        __syncthreads();

        // O += P @ V
        #pragma unroll
        for (int n = 0; n < 64; n++) {
            float a[4], bb[4];
            #pragma unroll
            for (int i = 0; i < 4; i++) a[i] = Ps[tr * 4 + i][n];
            #pragma unroll
            for (int j = 0; j < 4; j++) bb[j] = Vs[n][tc * 4 + j];
            #pragma unroll
            for (int i = 0; i < 4; i++)
                #pragma unroll
                for (int j = 0; j < 4; j++)
                    acc[i][j] += a[i] * bb[j];
        }
        __syncthreads();   // protect Kt/Vs/Ps before next tile's loads
    }

    // Epilogue: normalize and write out[b, q, h]
    #pragma unroll
    for (int i = 0; i < 4; i++) {
        const float inv_l = 1.0f / l_i[i];
        const int q = qb * 64 + tr * 4 + i;
        #pragma unroll
        for (int j = 0; j < 4; j++) {
            const int h = tc * 4 + j;
            out[((size_t)b * SEQ + q) * D_HEAD + h] = acc[i][j] * inv_l;
        }
    }
}

// ---------------------------------------------------------------------------
// Launch (no static state: attribute call is idempotent and made every call)
// ---------------------------------------------------------------------------
extern "C" void kernel_launch(void* const* d_in, const int* in_sizes, int n_in,
                              void* d_out, int out_size)
{
    const float* x  = (const float*)d_in[0];
    const float* Wq = (const float*)d_in[1];
    const float* bq = (const float*)d_in[2];
    const float* Wk = (const float*)d_in[3];
    const float* bk = (const float*)d_in[4];
    const float* Wv = (const float*)d_in[5];
    const float* bv = (const float*)d_in[6];
    float* out = (float*)d_out;

    proj_kernel<<<dim3(M_TOTAL / 64, 3), 256>>>(x, Wq, bq, Wk, bk, Wv, bv);

    const int smem_bytes = 4 * 64 * SPAD * sizeof(float);   // ~69.6 KB
    cudaFuncSetAttribute(attn_kernel,
                         cudaFuncAttributeMaxDynamicSharedMemorySize,
                         smem_bytes);
    attn_kernel<<<dim3(SEQ / 64, BATCH), 256, smem_bytes>>>(out);
}

// round 5
// speedup vs baseline: 2.6314x; 2.6314x over previous
#include <cuda_runtime.h>
#include <cuda_bf16.h>
#include <math.h>
#include <stdint.h>

#define D_MODEL 1024
#define D_HEAD  64
#define BATCH   4
#define SEQ     4096
#define M_TOTAL (BATCH * SEQ)   // 16384

// smem tile row stride in bytes (72 bf16 = 144B; 144 mod 128 = 16 -> ldmatrix
// rows hit distinct 16B bank groups, conflict-free)
#define ST 144

// ---------------------------------------------------------------------------
// Device-global scratch. Q/K/V stored as packed bf16 pairs along head dim:
// [row][32 words], hi and lo split parts. Q pre-scaled by 1/8.
// ---------------------------------------------------------------------------
__device__ uint32_t g_Qhi[M_TOTAL * 32], g_Qlo[M_TOTAL * 32];
__device__ uint32_t g_Khi[M_TOTAL * 32], g_Klo[M_TOTAL * 32];
__device__ uint32_t g_Vhi[M_TOTAL * 32], g_Vlo[M_TOTAL * 32];
__device__ float    g_Qn[M_TOTAL];      // per-row ||Q|| (scaled Q)
__device__ unsigned g_Kmax[BATCH];      // max ||K row|| bits (atomicMax on float bits)

// ---------------------------------------------------------------------------
// PTX helpers (all sm_80-era: valid on plain sm_100 target)
// ---------------------------------------------------------------------------
__device__ __forceinline__ uint32_t s2u(const void* p) {
    uint32_t a;
    asm("{ .reg .u64 t; cvta.to.shared.u64 t, %1; cvt.u32.u64 %0, t; }" : "=r"(a) : "l"(p));
    return a;
}
__device__ __forceinline__ void ldm4(uint32_t* r, uint32_t a) {
    asm volatile("ldmatrix.sync.aligned.m8n8.x4.shared.b16 {%0,%1,%2,%3}, [%4];"
                 : "=r"(r[0]), "=r"(r[1]), "=r"(r[2]), "=r"(r[3]) : "r"(a));
}
__device__ __forceinline__ void ldm4t(uint32_t* r, uint32_t a) {
    asm volatile("ldmatrix.sync.aligned.m8n8.x4.trans.shared.b16 {%0,%1,%2,%3}, [%4];"
                 : "=r"(r[0]), "=r"(r[1]), "=r"(r[2]), "=r"(r[3]) : "r"(a));
}
__device__ __forceinline__ void mma16816(float* d, const uint32_t* a, const uint32_t* b) {
    asm volatile(
        "mma.sync.aligned.m16n8k16.row.col.f32.bf16.bf16.f32 "
        "{%0,%1,%2,%3}, {%4,%5,%6,%7}, {%8,%9}, {%0,%1,%2,%3};"
        : "+f"(d[0]), "+f"(d[1]), "+f"(d[2]), "+f"(d[3])
        : "r"(a[0]), "r"(a[1]), "r"(a[2]), "r"(a[3]), "r"(b[0]), "r"(b[1]));
}
// pack (e0 -> low half, e1 -> high half)
__device__ __forceinline__ uint32_t packbf(float e0, float e1) {
    uint32_t d;
    asm("cvt.rn.bf16x2.f32 %0, %1, %2;" : "=r"(d) : "f"(e1), "f"(e0));
    return d;
}
// split pair of floats into bf16 hi word + bf16 residual-lo word
__device__ __forceinline__ void split2(float f0, float f1, uint32_t& hi, uint32_t& lo) {
    hi = packbf(f0, f1);
    __nv_bfloat162 h = *reinterpret_cast<__nv_bfloat162*>(&hi);
    lo = packbf(f0 - __bfloat162float(h.x), f1 - __bfloat162float(h.y));
}
__device__ __forceinline__ void sts8B(uint32_t addr, uint32_t a, uint32_t b) {
    asm volatile("st.shared.v2.b32 [%0], {%1,%2};" :: "r"(addr), "r"(a), "r"(b));
}
__device__ __forceinline__ void sts16B(uint32_t addr, uint4 v) {
    asm volatile("st.shared.v4.b32 [%0], {%1,%2,%3,%4};"
                 :: "r"(addr), "r"(v.x), "r"(v.y), "r"(v.z), "r"(v.w));
}

// ---------------------------------------------------------------------------
// Fused QKV projection, bf16x3 split precision via mma.sync.
// CTA = 128 rows of X, all three matrices. 256 threads = 8 warps x 16 rows.
// K = 1024 in 16 chunks of 64.
// smem: Xhi/Xlo [128 rows], Whi/Wlo [3 mats x 64 rows]  (92160 B)
// ---------------------------------------------------------------------------
#define PROJ_SMEM (2 * 128 * ST + 2 * 3 * 64 * ST)

__global__ __launch_bounds__(256) void proj_kernel(
    const float* __restrict__ x,
    const float* __restrict__ Wq, const float* __restrict__ bq,
    const float* __restrict__ Wk, const float* __restrict__ bk,
    const float* __restrict__ Wv, const float* __restrict__ bv)
{
    extern __shared__ __align__(16) uint8_t sm[];
    const uint32_t XHI = s2u(sm);
    const uint32_t XLO = XHI + 128 * ST;
    const uint32_t WHI = XLO + 128 * ST;             // + m*64*ST
    const uint32_t WLO = WHI + 3 * 64 * ST;

    const int tid  = threadIdx.x;
    const int lane = tid & 31;
    const int warp = tid >> 5;
    const int wr   = warp * 16;
    const int m0   = blockIdx.x * 128;

    const float* Wm[3] = { Wq, Wk, Wv };

    float acc[3][8][4];
    #pragma unroll
    for (int m = 0; m < 3; m++)
        #pragma unroll
        for (int j = 0; j < 8; j++)
            #pragma unroll
            for (int e = 0; e < 4; e++) acc[m][j][e] = 0.0f;

    for (int c = 0; c < 16; c++) {
        const int k0 = c * 64;
        // ---- stage X chunk (128 x 64 fp32 -> bf16 hi/lo smem) ----
        #pragma unroll
        for (int i = 0; i < 8; i++) {
            int idx = tid + i * 256;            // 2048 float4
            int row = idx >> 4, cg = idx & 15;
            float4 v = *(const float4*)&x[(size_t)(m0 + row) * D_MODEL + k0 + cg * 4];
            uint32_t h0, l0, h1, l1;
            split2(v.x, v.y, h0, l0);
            split2(v.z, v.w, h1, l1);
            uint32_t off = (uint32_t)(row * ST + cg * 8);
            sts8B(XHI + off, h0, h1);
            sts8B(XLO + off, l0, l1);
        }
        // ---- stage W chunks (3 mats x 64 x 64) ----
        #pragma unroll
        for (int m = 0; m < 3; m++) {
            #pragma unroll
            for (int i = 0; i < 4; i++) {
                int idx = tid + i * 256;        // 1024 float4
                int row = idx >> 4, cg = idx & 15;
                float4 v = *(const float4*)&Wm[m][(size_t)(k0 + row) * D_HEAD + cg * 4];
                uint32_t h0, l0, h1, l1;
                split2(v.x, v.y, h0, l0);
                split2(v.z, v.w, h1, l1);
                uint32_t off = (uint32_t)(m * 64 * ST + row * ST + cg * 8);
                sts8B(WHI + off, h0, h1);
                sts8B(WLO + off, l0, l1);
            }
        }
        __syncthreads();

        // ---- mma: terms hi*hi + hi*lo + lo*hi ----
        #pragma unroll
        for (int t = 0; t < 3; t++) {
            const uint32_t abase = (t == 2) ? XLO : XHI;
            const uint32_t bsel  = (t == 1) ? WLO : WHI;
            #pragma unroll
            for (int ks = 0; ks < 4; ks++) {
                uint32_t a[4];
                ldm4(a, abase + (uint32_t)((wr + (lane & 15)) * ST + ks * 32 + (lane >> 4) * 16));
                #pragma unroll
                for (int m = 0; m < 3; m++) {
                    const uint32_t bbase = bsel + (uint32_t)(m * 64 * ST);
                    #pragma unroll
                    for (int nt = 0; nt < 4; nt++) {
                        uint32_t bf[4];
                        ldm4t(bf, bbase + (uint32_t)((ks * 16 + (lane & 15)) * ST + nt * 32 + (lane >> 4) * 16));
                        mma16816(acc[m][2 * nt],     a, bf + 0);
                        mma16816(acc[m][2 * nt + 1], a, bf + 2);
                    }
                }
            }
        }
        __syncthreads();
    }

    // ---- epilogue ----
    const int r0g = m0 + wr + (lane >> 2);
    const int r1g = r0g + 8;
    const int bb  = r0g >> 12;   // batch (rows in a warp stay in one batch)

    // Q: bias, scale 1/8, split, store, row norm
    {
        float nsq0 = 0.0f, nsq1 = 0.0f;
        #pragma unroll
        for (int j = 0; j < 8; j++) {
            int h = j * 8 + 2 * (lane & 3);
            float b0 = __ldg(&bq[h]), b1 = __ldg(&bq[h + 1]);
            float v00 = (acc[0][j][0] + b0) * 0.125f, v01 = (acc[0][j][1] + b1) * 0.125f;
            float v10 = (acc[0][j][2] + b0) * 0.125f, v11 = (acc[0][j][3] + b1) * 0.125f;
            uint32_t hi, lo;
            split2(v00, v01, hi, lo);
            {
                __nv_bfloat162 H = *reinterpret_cast<__nv_bfloat162*>(&hi);
                __nv_bfloat162 L = *reinterpret_cast<__nv_bfloat162*>(&lo);
                float a0 = __bfloat162float(H.x) + __bfloat162float(L.x);
                float a1 = __bfloat162float(H.y) + __bfloat162float(L.y);
                nsq0 += a0 * a0 + a1 * a1;
            }
            g_Qhi[(size_t)r0g * 32 + h / 2] = hi;
            g_Qlo[(size_t)r0g * 32 + h / 2] = lo;
            split2(v10, v11, hi, lo);
            {
                __nv_bfloat162 H = *reinterpret_cast<__nv_bfloat162*>(&hi);
                __nv_bfloat162 L = *reinterpret_cast<__nv_bfloat162*>(&lo);
                float a0 = __bfloat162float(H.x) + __bfloat162float(L.x);
                float a1 = __bfloat162float(H.y) + __bfloat162float(L.y);
                nsq1 += a0 * a0 + a1 * a1;
            }
            g_Qhi[(size_t)r1g * 32 + h / 2] = hi;
            g_Qlo[(size_t)r1g * 32 + h / 2] = lo;
        }
        nsq0 += __shfl_xor_sync(0xffffffffu, nsq0, 1);
        nsq0 += __shfl_xor_sync(0xffffffffu, nsq0, 2);
        nsq1 += __shfl_xor_sync(0xffffffffu, nsq1, 1);
        nsq1 += __shfl_xor_sync(0xffffffffu, nsq1, 2);
        if ((lane & 3) == 0) {
            g_Qn[r0g] = sqrtf(nsq0);
            g_Qn[r1g] = sqrtf(nsq1);
        }
    }
    // K: bias, split, store, max row norm
    {
        float nsq0 = 0.0f, nsq1 = 0.0f;
        #pragma unroll
        for (int j = 0; j < 8; j++) {
            int h = j * 8 + 2 * (lane & 3);
            float b0 = __ldg(&bk[h]), b1 = __ldg(&bk[h + 1]);
            float v00 = acc[1][j][0] + b0, v01 = acc[1][j][1] + b1;
            float v10 = acc[1][j][2] + b0, v11 = acc[1][j][3] + b1;
            uint32_t hi, lo;
            split2(v00, v01, hi, lo);
            {
                __nv_bfloat162 H = *reinterpret_cast<__nv_bfloat162*>(&hi);
                __nv_bfloat162 L = *reinterpret_cast<__nv_bfloat162*>(&lo);
                float a0 = __bfloat162float(H.x) + __bfloat162float(L.x);
                float a1 = __bfloat162float(H.y) + __bfloat162float(L.y);
                nsq0 += a0 * a0 + a1 * a1;
            }
            g_Khi[(size_t)r0g * 32 + h / 2] = hi;
            g_Klo[(size_t)r0g * 32 + h / 2] = lo;
            split2(v10, v11, hi, lo);
            {
                __nv_bfloat162 H = *reinterpret_cast<__nv_bfloat162*>(&hi);
                __nv_bfloat162 L = *reinterpret_cast<__nv_bfloat162*>(&lo);
                float a0 = __bfloat162float(H.x) + __bfloat162float(L.x);
                float a1 = __bfloat162float(H.y) + __bfloat162float(L.y);
                nsq1 += a0 * a0 + a1 * a1;
            }
            g_Khi[(size_t)r1g * 32 + h / 2] = hi;
            g_Klo[(size_t)r1g * 32 + h / 2] = lo;
        }
        nsq0 += __shfl_xor_sync(0xffffffffu, nsq0, 1);
        nsq0 += __shfl_xor_sync(0xffffffffu, nsq0, 2);
        nsq1 += __shfl_xor_sync(0xffffffffu, nsq1, 1);
        nsq1 += __shfl_xor_sync(0xffffffffu, nsq1, 2);
        if ((lane & 3) == 0) {
            float mx = fmaxf(sqrtf(nsq0), sqrtf(nsq1));
            atomicMax(&g_Kmax[bb], __float_as_uint(mx));
        }
    }
    // V: bias, split, store
    {
        #pragma unroll
        for (int j = 0; j < 8; j++) {
            int h = j * 8 + 2 * (lane & 3);
            float b0 = __ldg(&bv[h]), b1 = __ldg(&bv[h + 1]);
            uint32_t hi, lo;
            split2(acc[2][j][0] + b0, acc[2][j][1] + b1, hi, lo);
            g_Vhi[(size_t)r0g * 32 + h / 2] = hi;
            g_Vlo[(size_t)r0g * 32 + h / 2] = lo;
            split2(acc[2][j][2] + b0, acc[2][j][3] + b1, hi, lo);
            g_Vhi[(size_t)r1g * 32 + h / 2] = hi;
            g_Vlo[(size_t)r1g * 32 + h / 2] = lo;
        }
    }
}

// ---------------------------------------------------------------------------
// Flash attention, bf16x3 mma.sync, bound-softmax (no rescale, O in fp32 frags).
// CTA = 64 q rows of one batch, 128 threads = 4 warps x 16 rows.
// Key tiles of 64; masking only on the diagonal tile (kb == qt).
// smem: Qhi/Qlo/Khi/Klo/Vhi/Vlo [64 rows each] + bnd[64]  (~55.5 KB)
// ---------------------------------------------------------------------------
#define ATTN_SMEM (6 * 64 * ST + 64 * 4)

__global__ __launch_bounds__(128) void attn_kernel(float* __restrict__ out)
{
    extern __shared__ __align__(16) uint8_t sm[];
    const uint32_t QHI = s2u(sm);
    const uint32_t QLO = QHI + 64 * ST;
    const uint32_t KHI = QLO + 64 * ST;
    const uint32_t KLO = KHI + 64 * ST;
    const uint32_t VHI = KLO + 64 * ST;
    const uint32_t VLO = VHI + 64 * ST;
    float* BND = (float*)(sm + 6 * 64 * ST);

    const int tid  = threadIdx.x;
    const int lane = tid & 31;
    const int warp = tid >> 5;
    const int wr   = warp * 16;
    const int b    = blockIdx.y;
    const int qt   = (gridDim.x - 1) - blockIdx.x;   // heaviest first
    const int q0   = qt * 64;

    // ---- stage Q tile + bounds ----
    #pragma unroll
    for (int i = 0; i < 4; i++) {
        int idx = tid + i * 128;          // 512 16B chunks per array
        int row = idx >> 3, cg = idx & 7;
        size_t g = (size_t)(b * SEQ + q0 + row) * 32 + cg * 4;
        sts16B(QHI + (uint32_t)(row * ST + cg * 16), *(const uint4*)&g_Qhi[g]);
        sts16B(QLO + (uint32_t)(row * ST + cg * 16), *(const uint4*)&g_Qlo[g]);
    }
    {
        float kmax = __uint_as_float(g_Kmax[b]);
        if (tid < 64) BND[tid] = g_Qn[b * SEQ + q0 + tid] * kmax + 1.0f;
    }
    __syncthreads();

    float o[8][4];
    #pragma unroll
    for (int j = 0; j < 8; j++)
        #pragma unroll
        for (int e = 0; e < 4; e++) o[j][e] = 0.0f;
    float lsum0 = 0.0f, lsum1 = 0.0f;

    const float bnd0 = BND[wr + (lane >> 2)];
    const float bnd1 = BND[wr + (lane >> 2) + 8];
    const int   qg0  = q0 + wr + (lane >> 2);
    const int   qg1  = qg0 + 8;

    for (int kb = 0; kb <= qt; kb++) {
        // ---- stage K/V tiles ----
        #pragma unroll
        for (int i = 0; i < 4; i++) {
            int idx = tid + i * 128;
            int row = idx >> 3, cg = idx & 7;
            size_t g = (size_t)(b * SEQ + kb * 64 + row) * 32 + cg * 4;
            uint32_t off = (uint32_t)(row * ST + cg * 16);
            sts16B(KHI + off, *(const uint4*)&g_Khi[g]);
            sts16B(KLO + off, *(const uint4*)&g_Klo[g]);
            sts16B(VHI + off, *(const uint4*)&g_Vhi[g]);
            sts16B(VLO + off, *(const uint4*)&g_Vlo[g]);
        }
        __syncthreads();

        // ---- S = Q K^T (3 split terms) ----
        float s[8][4];
        #pragma unroll
        for (int j = 0; j < 8; j++)
            #pragma unroll
            for (int e = 0; e < 4; e++) s[j][e] = 0.0f;

        #pragma unroll
        for (int t = 0; t < 3; t++) {
            const uint32_t abase = (t == 2) ? QLO : QHI;
            const uint32_t bbase = (t == 1) ? KLO : KHI;
            #pragma unroll
            for (int ks = 0; ks < 4; ks++) {
                uint32_t a[4];
                ldm4(a, abase + (uint32_t)((wr + (lane & 15)) * ST + ks * 32 + (lane >> 4) * 16));
                #pragma unroll
                for (int nt = 0; nt < 4; nt++) {
                    uint32_t kf[4];
                    ldm4(kf, bbase + (uint32_t)((nt * 16 + (lane & 15)) * ST + ks * 32 + (lane >> 4) * 16));
                    uint32_t b0[2] = { kf[0], kf[2] };
                    uint32_t b1[2] = { kf[1], kf[3] };
                    mma16816(s[2 * nt],     a, b0);
                    mma16816(s[2 * nt + 1], a, b1);
                }
            }
        }

        // ---- softmax (fixed bound) + pack P to bf16 hi/lo A-frags ----
        uint32_t pah[4][4], pal[4][4];
        const bool diag = (kb == qt);
        #pragma unroll
        for (int j = 0; j < 8; j++) {
            int key = kb * 64 + j * 8 + 2 * (lane & 3);
            float p00 = __expf(s[j][0] - bnd0);
            float p01 = __expf(s[j][1] - bnd0);
            float p10 = __expf(s[j][2] - bnd1);
            float p11 = __expf(s[j][3] - bnd1);
            if (diag) {
                if (key     > qg0) p00 = 0.0f;
                if (key + 1 > qg0) p01 = 0.0f;
                if (key     > qg1) p10 = 0.0f;
                if (key + 1 > qg1) p11 = 0.0f;
            }
            lsum0 += p00 + p01;
            lsum1 += p10 + p11;
            int ks = j >> 1, half = j & 1;
            uint32_t w0, w1, l0, l1;
            split2(p00, p01, w0, l0);
            split2(p10, p11, w1, l1);
            pah[ks][half * 2 + 0] = w0;
            pah[ks][half * 2 + 1] = w1;
            pal[ks][half * 2 + 0] = l0;
            pal[ks][half * 2 + 1] = l1;
        }

        // ---- O += P V (3 split terms) ----
        #pragma unroll
        for (int t = 0; t < 3; t++) {
            uint32_t (*pa)[4] = (t == 1) ? pal : pah;
            const uint32_t vbase = (t == 2) ? VLO : VHI;
            #pragma unroll
            for (int ks = 0; ks < 4; ks++) {
                #pragma unroll
                for (int nt = 0; nt < 4; nt++) {
                    uint32_t vf[4];
                    ldm4t(vf, vbase + (uint32_t)((ks * 16 + (lane & 15)) * ST + nt * 32 + (lane >> 4) * 16));
                    mma16816(o[2 * nt],     pa[ks], vf + 0);
                    mma16816(o[2 * nt + 1], pa[ks], vf + 2);
                }
            }
        }
        __syncthreads();
    }

    // ---- epilogue: reduce l over quad, normalize, store ----
    lsum0 += __shfl_xor_sync(0xffffffffu, lsum0, 1);
    lsum0 += __shfl_xor_sync(0xffffffffu, lsum0, 2);
    lsum1 += __shfl_xor_sync(0xffffffffu, lsum1, 1);
    lsum1 += __shfl_xor_sync(0xffffffffu, lsum1, 2);
    const float inv0 = 1.0f / lsum0;
    const float inv1 = 1.0f / lsum1;
    const size_t row0 = (size_t)(b * SEQ + qg0);
    const size_t row1 = (size_t)(b * SEQ + qg1);
    #pragma unroll
    for (int j = 0; j < 8; j++) {
        int h = j * 8 + 2 * (lane & 3);
        float2 v0 = { o[j][0] * inv0, o[j][1] * inv0 };
        float2 v1 = { o[j][2] * inv1, o[j][3] * inv1 };
        *(float2*)&out[row0 * D_HEAD + h] = v0;
        *(float2*)&out[row1 * D_HEAD + h] = v1;
    }
}

// ---------------------------------------------------------------------------
// Launch
// ---------------------------------------------------------------------------
extern "C" void kernel_launch(void* const* d_in, const int* in_sizes, int n_in,
                              void* d_out, int out_size)
{
    const float* x  = (const float*)d_in[0];
    const float* Wq = (const float*)d_in[1];
    const float* bq = (const float*)d_in[2];
    const float* Wk = (const float*)d_in[3];
    const float* bk = (const float*)d_in[4];
    const float* Wv = (const float*)d_in[5];
    const float* bv = (const float*)d_in[6];
    float* out = (float*)d_out;

    cudaFuncSetAttribute(proj_kernel, cudaFuncAttributeMaxDynamicSharedMemorySize, PROJ_SMEM);
    cudaFuncSetAttribute(attn_kernel, cudaFuncAttributeMaxDynamicSharedMemorySize, ATTN_SMEM);

    proj_kernel<<<M_TOTAL / 128, 256, PROJ_SMEM>>>(x, Wq, bq, Wk, bk, Wv, bv);
    attn_kernel<<<dim3(SEQ / 64, BATCH), 128, ATTN_SMEM>>>(out);
}

// round 6
// speedup vs baseline: 2.8648x; 1.0887x over previous
#include <cuda_runtime.h>
#include <cuda_bf16.h>
#include <math.h>
#include <stdint.h>

#define D_MODEL 1024
#define D_HEAD  64
#define BATCH   4
#define SEQ     4096
#define M_TOTAL (BATCH * SEQ)   // 16384

// smem tile row stride in bytes (72 bf16 = 144B; 144 mod 128 = 16 -> ldmatrix
// rows hit distinct 16B bank groups, conflict-free)
#define ST 144

// ---------------------------------------------------------------------------
// Device-global scratch. Q/K/V stored as packed bf16 pairs along head dim:
// [row][32 words], hi and lo split parts. Q pre-scaled by 1/8.
// ---------------------------------------------------------------------------
__device__ uint32_t g_Qhi[M_TOTAL * 32], g_Qlo[M_TOTAL * 32];
__device__ uint32_t g_Khi[M_TOTAL * 32], g_Klo[M_TOTAL * 32];
__device__ uint32_t g_Vhi[M_TOTAL * 32], g_Vlo[M_TOTAL * 32];
__device__ float    g_Qn[M_TOTAL];      // per-row ||Q|| (scaled Q)
__device__ unsigned g_Kmax[BATCH];      // max ||K row|| bits (atomicMax on float bits)

// ---------------------------------------------------------------------------
// PTX helpers (all sm_80-era: valid on plain sm_100 target)
// ---------------------------------------------------------------------------
__device__ __forceinline__ uint32_t s2u(const void* p) {
    uint32_t a;
    asm("{ .reg .u64 t; cvta.to.shared.u64 t, %1; cvt.u32.u64 %0, t; }" : "=r"(a) : "l"(p));
    return a;
}
__device__ __forceinline__ void ldm4(uint32_t* r, uint32_t a) {
    asm volatile("ldmatrix.sync.aligned.m8n8.x4.shared.b16 {%0,%1,%2,%3}, [%4];"
                 : "=r"(r[0]), "=r"(r[1]), "=r"(r[2]), "=r"(r[3]) : "r"(a));
}
__device__ __forceinline__ void ldm4t(uint32_t* r, uint32_t a) {
    asm volatile("ldmatrix.sync.aligned.m8n8.x4.trans.shared.b16 {%0,%1,%2,%3}, [%4];"
                 : "=r"(r[0]), "=r"(r[1]), "=r"(r[2]), "=r"(r[3]) : "r"(a));
}
__device__ __forceinline__ void mma16816(float* d, const uint32_t* a, const uint32_t* b) {
    asm volatile(
        "mma.sync.aligned.m16n8k16.row.col.f32.bf16.bf16.f32 "
        "{%0,%1,%2,%3}, {%4,%5,%6,%7}, {%8,%9}, {%0,%1,%2,%3};"
        : "+f"(d[0]), "+f"(d[1]), "+f"(d[2]), "+f"(d[3])
        : "r"(a[0]), "r"(a[1]), "r"(a[2]), "r"(a[3]), "r"(b[0]), "r"(b[1]));
}
// pack (e0 -> low half, e1 -> high half)
__device__ __forceinline__ uint32_t packbf(float e0, float e1) {
    uint32_t d;
    asm("cvt.rn.bf16x2.f32 %0, %1, %2;" : "=r"(d) : "f"(e1), "f"(e0));
    return d;
}
// split pair of floats into bf16 hi word + bf16 residual-lo word
__device__ __forceinline__ void split2(float f0, float f1, uint32_t& hi, uint32_t& lo) {
    hi = packbf(f0, f1);
    __nv_bfloat162 h = *reinterpret_cast<__nv_bfloat162*>(&hi);
    lo = packbf(f0 - __bfloat162float(h.x), f1 - __bfloat162float(h.y));
}
__device__ __forceinline__ void sts8B(uint32_t addr, uint32_t a, uint32_t b) {
    asm volatile("st.shared.v2.b32 [%0], {%1,%2};" :: "r"(addr), "r"(a), "r"(b));
}
__device__ __forceinline__ void sts16B(uint32_t addr, uint4 v) {
    asm volatile("st.shared.v4.b32 [%0], {%1,%2,%3,%4};"
                 :: "r"(addr), "r"(v.x), "r"(v.y), "r"(v.z), "r"(v.w));
}

// ---------------------------------------------------------------------------
// Fused QKV projection, bf16x3 split precision via mma.sync.
// CTA = 128 rows of X, all three matrices. 256 threads = 8 warps x 16 rows.
// K = 1024 in 16 chunks of 64.
// ---------------------------------------------------------------------------
#define PROJ_SMEM (2 * 128 * ST + 2 * 3 * 64 * ST)

__global__ __launch_bounds__(256) void proj_kernel(
    const float* __restrict__ x,
    const float* __restrict__ Wq, const float* __restrict__ bq,
    const float* __restrict__ Wk, const float* __restrict__ bk,
    const float* __restrict__ Wv, const float* __restrict__ bv)
{
    extern __shared__ __align__(16) uint8_t sm[];
    const uint32_t XHI = s2u(sm);
    const uint32_t XLO = XHI + 128 * ST;
    const uint32_t WHI = XLO + 128 * ST;             // + m*64*ST
    const uint32_t WLO = WHI + 3 * 64 * ST;

    const int tid  = threadIdx.x;
    const int lane = tid & 31;
    const int warp = tid >> 5;
    const int wr   = warp * 16;
    const int m0   = blockIdx.x * 128;

    const float* Wm[3] = { Wq, Wk, Wv };

    float acc[3][8][4];
    #pragma unroll
    for (int m = 0; m < 3; m++)
        #pragma unroll
        for (int j = 0; j < 8; j++)
            #pragma unroll
            for (int e = 0; e < 4; e++) acc[m][j][e] = 0.0f;

    for (int c = 0; c < 16; c++) {
        const int k0 = c * 64;
        #pragma unroll
        for (int i = 0; i < 8; i++) {
            int idx = tid + i * 256;
            int row = idx >> 4, cg = idx & 15;
            float4 v = *(const float4*)&x[(size_t)(m0 + row) * D_MODEL + k0 + cg * 4];
            uint32_t h0, l0, h1, l1;
            split2(v.x, v.y, h0, l0);
            split2(v.z, v.w, h1, l1);
            uint32_t off = (uint32_t)(row * ST + cg * 8);
            sts8B(XHI + off, h0, h1);
            sts8B(XLO + off, l0, l1);
        }
        #pragma unroll
        for (int m = 0; m < 3; m++) {
            #pragma unroll
            for (int i = 0; i < 4; i++) {
                int idx = tid + i * 256;
                int row = idx >> 4, cg = idx & 15;
                float4 v = *(const float4*)&Wm[m][(size_t)(k0 + row) * D_HEAD + cg * 4];
                uint32_t h0, l0, h1, l1;
                split2(v.x, v.y, h0, l0);
                split2(v.z, v.w, h1, l1);
                uint32_t off = (uint32_t)(m * 64 * ST + row * ST + cg * 8);
                sts8B(WHI + off, h0, h1);
                sts8B(WLO + off, l0, l1);
            }
        }
        __syncthreads();

        #pragma unroll
        for (int t = 0; t < 3; t++) {
            const uint32_t abase = (t == 2) ? XLO : XHI;
            const uint32_t bsel  = (t == 1) ? WLO : WHI;
            #pragma unroll
            for (int ks = 0; ks < 4; ks++) {
                uint32_t a[4];
                ldm4(a, abase + (uint32_t)((wr + (lane & 15)) * ST + ks * 32 + (lane >> 4) * 16));
                #pragma unroll
                for (int m = 0; m < 3; m++) {
                    const uint32_t bbase = bsel + (uint32_t)(m * 64 * ST);
                    #pragma unroll
                    for (int nt = 0; nt < 4; nt++) {
                        uint32_t bf[4];
                        ldm4t(bf, bbase + (uint32_t)((ks * 16 + (lane & 15)) * ST + nt * 32 + (lane >> 4) * 16));
                        mma16816(acc[m][2 * nt],     a, bf + 0);
                        mma16816(acc[m][2 * nt + 1], a, bf + 2);
                    }
                }
            }
        }
        __syncthreads();
    }

    // ---- epilogue ----
    const int r0g = m0 + wr + (lane >> 2);
    const int r1g = r0g + 8;
    const int bb  = r0g >> 12;

    {   // Q
        float nsq0 = 0.0f, nsq1 = 0.0f;
        #pragma unroll
        for (int j = 0; j < 8; j++) {
            int h = j * 8 + 2 * (lane & 3);
            float b0 = __ldg(&bq[h]), b1 = __ldg(&bq[h + 1]);
            float v00 = (acc[0][j][0] + b0) * 0.125f, v01 = (acc[0][j][1] + b1) * 0.125f;
            float v10 = (acc[0][j][2] + b0) * 0.125f, v11 = (acc[0][j][3] + b1) * 0.125f;
            uint32_t hi, lo;
            split2(v00, v01, hi, lo);
            {
                __nv_bfloat162 H = *reinterpret_cast<__nv_bfloat162*>(&hi);
                __nv_bfloat162 L = *reinterpret_cast<__nv_bfloat162*>(&lo);
                float a0 = __bfloat162float(H.x) + __bfloat162float(L.x);
                float a1 = __bfloat162float(H.y) + __bfloat162float(L.y);
                nsq0 += a0 * a0 + a1 * a1;
            }
            g_Qhi[(size_t)r0g * 32 + h / 2] = hi;
            g_Qlo[(size_t)r0g * 32 + h / 2] = lo;
            split2(v10, v11, hi, lo);
            {
                __nv_bfloat162 H = *reinterpret_cast<__nv_bfloat162*>(&hi);
                __nv_bfloat162 L = *reinterpret_cast<__nv_bfloat162*>(&lo);
                float a0 = __bfloat162float(H.x) + __bfloat162float(L.x);
                float a1 = __bfloat162float(H.y) + __bfloat162float(L.y);
                nsq1 += a0 * a0 + a1 * a1;
            }
            g_Qhi[(size_t)r1g * 32 + h / 2] = hi;
            g_Qlo[(size_t)r1g * 32 + h / 2] = lo;
        }
        nsq0 += __shfl_xor_sync(0xffffffffu, nsq0, 1);
        nsq0 += __shfl_xor_sync(0xffffffffu, nsq0, 2);
        nsq1 += __shfl_xor_sync(0xffffffffu, nsq1, 1);
        nsq1 += __shfl_xor_sync(0xffffffffu, nsq1, 2);
        if ((lane & 3) == 0) {
            g_Qn[r0g] = sqrtf(nsq0);
            g_Qn[r1g] = sqrtf(nsq1);
        }
    }
    {   // K
        float nsq0 = 0.0f, nsq1 = 0.0f;
        #pragma unroll
        for (int j = 0; j < 8; j++) {
            int h = j * 8 + 2 * (lane & 3);
            float b0 = __ldg(&bk[h]), b1 = __ldg(&bk[h + 1]);
            float v00 = acc[1][j][0] + b0, v01 = acc[1][j][1] + b1;
            float v10 = acc[1][j][2] + b0, v11 = acc[1][j][3] + b1;
            uint32_t hi, lo;
            split2(v00, v01, hi, lo);
            {
                __nv_bfloat162 H = *reinterpret_cast<__nv_bfloat162*>(&hi);
                __nv_bfloat162 L = *reinterpret_cast<__nv_bfloat162*>(&lo);
                float a0 = __bfloat162float(H.x) + __bfloat162float(L.x);
                float a1 = __bfloat162float(H.y) + __bfloat162float(L.y);
                nsq0 += a0 * a0 + a1 * a1;
            }
            g_Khi[(size_t)r0g * 32 + h / 2] = hi;
            g_Klo[(size_t)r0g * 32 + h / 2] = lo;
            split2(v10, v11, hi, lo);
            {
                __nv_bfloat162 H = *reinterpret_cast<__nv_bfloat162*>(&hi);
                __nv_bfloat162 L = *reinterpret_cast<__nv_bfloat162*>(&lo);
                float a0 = __bfloat162float(H.x) + __bfloat162float(L.x);
                float a1 = __bfloat162float(H.y) + __bfloat162float(L.y);
                nsq1 += a0 * a0 + a1 * a1;
            }
            g_Khi[(size_t)r1g * 32 + h / 2] = hi;
            g_Klo[(size_t)r1g * 32 + h / 2] = lo;
        }
        nsq0 += __shfl_xor_sync(0xffffffffu, nsq0, 1);
        nsq0 += __shfl_xor_sync(0xffffffffu, nsq0, 2);
        nsq1 += __shfl_xor_sync(0xffffffffu, nsq1, 1);
        nsq1 += __shfl_xor_sync(0xffffffffu, nsq1, 2);
        if ((lane & 3) == 0) {
            float mx = fmaxf(sqrtf(nsq0), sqrtf(nsq1));
            atomicMax(&g_Kmax[bb], __float_as_uint(mx));
        }
    }
    {   // V
        #pragma unroll
        for (int j = 0; j < 8; j++) {
            int h = j * 8 + 2 * (lane & 3);
            float b0 = __ldg(&bv[h]), b1 = __ldg(&bv[h + 1]);
            uint32_t hi, lo;
            split2(acc[2][j][0] + b0, acc[2][j][1] + b1, hi, lo);
            g_Vhi[(size_t)r0g * 32 + h / 2] = hi;
            g_Vlo[(size_t)r0g * 32 + h / 2] = lo;
            split2(acc[2][j][2] + b0, acc[2][j][3] + b1, hi, lo);
            g_Vhi[(size_t)r1g * 32 + h / 2] = hi;
            g_Vlo[(size_t)r1g * 32 + h / 2] = lo;
        }
    }
}

// ---------------------------------------------------------------------------
// Flash attention, bf16x3 mma.sync, bound-softmax, split-K across warp halves.
// CTA = 64 q rows of one batch, 256 threads = 8 warps.
//   warp w: wq = w&3 -> q rows wq*16..+15, wh = w>>2 -> key half of 128-key tile
// Key tiles of 128. Each warp-half accumulates partial O/l; cross-warp smem
// reduction at the end. Masking only on the last tile.
// smem: Qhi/Qlo [64 rows] + Khi/Klo/Vhi/Vlo [128 rows] + bnd[64]  (~92 KB)
// ---------------------------------------------------------------------------
#define ATTN_SMEM (2 * 64 * ST + 4 * 128 * ST + 64 * 4)

__global__ __launch_bounds__(256) void attn_kernel(float* __restrict__ out)
{
    extern __shared__ __align__(16) uint8_t sm[];
    const uint32_t QHI = s2u(sm);
    const uint32_t QLO = QHI + 64 * ST;
    const uint32_t KHI = QLO + 64 * ST;
    const uint32_t KLO = KHI + 128 * ST;
    const uint32_t VHI = KLO + 128 * ST;
    const uint32_t VLO = VHI + 128 * ST;
    float* BND = (float*)(sm + 2 * 64 * ST + 4 * 128 * ST);
    // end-of-loop reduction overlays (inside the K/V region, used after loop)
    float* OV = (float*)(sm + 2 * 64 * ST);                 // 4*32*36 floats
    float* LV = (float*)(sm + 2 * 64 * ST + 4 * 32 * 36 * 4);

    const int tid  = threadIdx.x;
    const int lane = tid & 31;
    const int warp = tid >> 5;
    const int wq   = warp & 3;
    const int wh   = warp >> 2;
    const int wr   = wq * 16;
    const int b    = blockIdx.y;
    const int qt   = (gridDim.x - 1) - blockIdx.x;   // heaviest first
    const int q0   = qt * 64;

    // ---- stage Q tile + bounds ----
    #pragma unroll
    for (int i = 0; i < 2; i++) {
        int idx = tid + i * 256;          // 512 16B chunks per array
        int row = idx >> 3, cg = idx & 7;
        size_t g = (size_t)(b * SEQ + q0 + row) * 32 + cg * 4;
        sts16B(QHI + (uint32_t)(row * ST + cg * 16), *(const uint4*)&g_Qhi[g]);
        sts16B(QLO + (uint32_t)(row * ST + cg * 16), *(const uint4*)&g_Qlo[g]);
    }
    {
        float kmax = __uint_as_float(g_Kmax[b]);
        if (tid < 64) BND[tid] = g_Qn[b * SEQ + q0 + tid] * kmax + 1.0f;
    }
    __syncthreads();

    float o[8][4];
    #pragma unroll
    for (int j = 0; j < 8; j++)
        #pragma unroll
        for (int e = 0; e < 4; e++) o[j][e] = 0.0f;
    float lsum0 = 0.0f, lsum1 = 0.0f;

    const float bnd0 = BND[wr + (lane >> 2)];
    const float bnd1 = BND[wr + (lane >> 2) + 8];
    const int   qg0  = q0 + wr + (lane >> 2);
    const int   qg1  = qg0 + 8;
    const int   qmxw = q0 + wr + 15;                 // max q row of this warp

    const int n_tiles = (q0 + 64 + 127) >> 7;        // 128-key tiles

    for (int kb = 0; kb < n_tiles; kb++) {
        // ---- stage K/V tiles (128 rows x 4 arrays) ----
        #pragma unroll
        for (int i = 0; i < 4; i++) {
            int idx = tid + i * 256;                 // 1024 16B chunks / array
            int row = idx >> 3, cg = idx & 7;
            size_t g = (size_t)(b * SEQ + kb * 128 + row) * 32 + cg * 4;
            uint32_t off = (uint32_t)(row * ST + cg * 16);
            sts16B(KHI + off, *(const uint4*)&g_Khi[g]);
            sts16B(KLO + off, *(const uint4*)&g_Klo[g]);
            sts16B(VHI + off, *(const uint4*)&g_Vhi[g]);
            sts16B(VLO + off, *(const uint4*)&g_Vlo[g]);
        }
        __syncthreads();

        const int keybase = kb * 128 + wh * 64;
        if (keybase <= qmxw) {
            // ---- S = Q K^T over this warp's 64-key half (3 split terms) ----
            float s[8][4];
            #pragma unroll
            for (int j = 0; j < 8; j++)
                #pragma unroll
                for (int e = 0; e < 4; e++) s[j][e] = 0.0f;

            #pragma unroll
            for (int t = 0; t < 3; t++) {
                const uint32_t abase = (t == 2) ? QLO : QHI;
                const uint32_t bbase = (t == 1) ? KLO : KHI;
                #pragma unroll
                for (int ks = 0; ks < 4; ks++) {
                    uint32_t a[4];
                    ldm4(a, abase + (uint32_t)((wr + (lane & 15)) * ST + ks * 32 + (lane >> 4) * 16));
                    #pragma unroll
                    for (int nt = 0; nt < 4; nt++) {
                        uint32_t kf[4];
                        ldm4(kf, bbase + (uint32_t)((wh * 64 + nt * 16 + (lane & 15)) * ST + ks * 32 + (lane >> 4) * 16));
                        uint32_t b0[2] = { kf[0], kf[2] };
                        uint32_t b1[2] = { kf[1], kf[3] };
                        mma16816(s[2 * nt],     a, b0);
                        mma16816(s[2 * nt + 1], a, b1);
                    }
                }
            }

            // ---- softmax (fixed bound) + pack P to bf16 hi/lo A-frags ----
            uint32_t pah[4][4], pal[4][4];
            const bool diag = (kb == n_tiles - 1);
            #pragma unroll
            for (int j = 0; j < 8; j++) {
                int key = keybase + j * 8 + 2 * (lane & 3);
                float p00 = __expf(s[j][0] - bnd0);
                float p01 = __expf(s[j][1] - bnd0);
                float p10 = __expf(s[j][2] - bnd1);
                float p11 = __expf(s[j][3] - bnd1);
                if (diag) {
                    if (key     > qg0) p00 = 0.0f;
                    if (key + 1 > qg0) p01 = 0.0f;
                    if (key     > qg1) p10 = 0.0f;
                    if (key + 1 > qg1) p11 = 0.0f;
                }
                lsum0 += p00 + p01;
                lsum1 += p10 + p11;
                int ks = j >> 1, half = j & 1;
                uint32_t w0, w1, l0, l1;
                split2(p00, p01, w0, l0);
                split2(p10, p11, w1, l1);
                pah[ks][half * 2 + 0] = w0;
                pah[ks][half * 2 + 1] = w1;
                pal[ks][half * 2 + 0] = l0;
                pal[ks][half * 2 + 1] = l1;
            }

            // ---- O += P V over this warp's 64 V rows (3 split terms) ----
            #pragma unroll
            for (int t = 0; t < 3; t++) {
                uint32_t (*pa)[4] = (t == 1) ? pal : pah;
                const uint32_t vbase = (t == 2) ? VLO : VHI;
                #pragma unroll
                for (int ks = 0; ks < 4; ks++) {
                    #pragma unroll
                    for (int nt = 0; nt < 4; nt++) {
                        uint32_t vf[4];
                        ldm4t(vf, vbase + (uint32_t)((wh * 64 + ks * 16 + (lane & 15)) * ST + nt * 32 + (lane >> 4) * 16));
                        mma16816(o[2 * nt],     pa[ks], vf + 0);
                        mma16816(o[2 * nt + 1], pa[ks], vf + 2);
                    }
                }
            }
        }
        __syncthreads();
    }

    // ---- cross-warp reduction: wh=1 partials -> wh=0 ----
    if (wh == 1) {
        float* dst = OV + (size_t)(wq * 32 + lane) * 36;
        #pragma unroll
        for (int j = 0; j < 8; j++)
            #pragma unroll
            for (int e = 0; e < 4; e++) dst[j * 4 + e] = o[j][e];
        LV[(wq * 32 + lane) * 2 + 0] = lsum0;
        LV[(wq * 32 + lane) * 2 + 1] = lsum1;
    }
    __syncthreads();
    if (wh == 0) {
        const float* src = OV + (size_t)(wq * 32 + lane) * 36;
        #pragma unroll
        for (int j = 0; j < 8; j++)
            #pragma unroll
            for (int e = 0; e < 4; e++) o[j][e] += src[j * 4 + e];
        lsum0 += LV[(wq * 32 + lane) * 2 + 0];
        lsum1 += LV[(wq * 32 + lane) * 2 + 1];

        lsum0 += __shfl_xor_sync(0xffffffffu, lsum0, 1);
        lsum0 += __shfl_xor_sync(0xffffffffu, lsum0, 2);
        lsum1 += __shfl_xor_sync(0xffffffffu, lsum1, 1);
        lsum1 += __shfl_xor_sync(0xffffffffu, lsum1, 2);
        const float inv0 = 1.0f / lsum0;
        const float inv1 = 1.0f / lsum1;
        const size_t row0 = (size_t)(b * SEQ + qg0);
        const size_t row1 = (size_t)(b * SEQ + qg1);
        #pragma unroll
        for (int j = 0; j < 8; j++) {
            int h = j * 8 + 2 * (lane & 3);
            float2 v0 = { o[j][0] * inv0, o[j][1] * inv0 };
            float2 v1 = { o[j][2] * inv1, o[j][3] * inv1 };
            *(float2*)&out[row0 * D_HEAD + h] = v0;
            *(float2*)&out[row1 * D_HEAD + h] = v1;
        }
    }
}

// ---------------------------------------------------------------------------
// Launch
// ---------------------------------------------------------------------------
extern "C" void kernel_launch(void* const* d_in, const int* in_sizes, int n_in,
                              void* d_out, int out_size)
{
    const float* x  = (const float*)d_in[0];
    const float* Wq = (const float*)d_in[1];
    const float* bq = (const float*)d_in[2];
    const float* Wk = (const float*)d_in[3];
    const float* bk = (const float*)d_in[4];
    const float* Wv = (const float*)d_in[5];
    const float* bv = (const float*)d_in[6];
    float* out = (float*)d_out;

    cudaFuncSetAttribute(proj_kernel, cudaFuncAttributeMaxDynamicSharedMemorySize, PROJ_SMEM);
    cudaFuncSetAttribute(attn_kernel, cudaFuncAttributeMaxDynamicSharedMemorySize, ATTN_SMEM);

    proj_kernel<<<M_TOTAL / 128, 256, PROJ_SMEM>>>(x, Wq, bq, Wk, bk, Wv, bv);
    attn_kernel<<<dim3(SEQ / 64, BATCH), 256, ATTN_SMEM>>>(out);
}

// round 7
// speedup vs baseline: 2.9522x; 1.0305x over previous
#include <cuda_runtime.h>
#include <cuda_bf16.h>
#include <math.h>
#include <stdint.h>

#define D_MODEL 1024
#define D_HEAD  64
#define BATCH   4
#define SEQ     4096
#define M_TOTAL (BATCH * SEQ)   // 16384

// smem tile row stride in bytes (72 bf16 = 144B; 144 mod 128 = 16 -> ldmatrix
// rows hit distinct 16B bank groups, conflict-free)
#define ST 144

// ---------------------------------------------------------------------------
// Device-global scratch. Q/K/V stored as packed bf16 pairs along head dim:
// [row][32 words], hi and lo split parts. Q pre-scaled by 1/8.
// ---------------------------------------------------------------------------
__device__ uint32_t g_Qhi[M_TOTAL * 32], g_Qlo[M_TOTAL * 32];
__device__ uint32_t g_Khi[M_TOTAL * 32], g_Klo[M_TOTAL * 32];
__device__ uint32_t g_Vhi[M_TOTAL * 32], g_Vlo[M_TOTAL * 32];
__device__ float    g_Qn[M_TOTAL];      // per-row ||Q|| (scaled Q)
__device__ unsigned g_Kmax[BATCH];      // max ||K row|| bits (atomicMax on float bits)

// ---------------------------------------------------------------------------
// PTX helpers (all sm_80-era: valid on plain sm_100 target)
// ---------------------------------------------------------------------------
__device__ __forceinline__ uint32_t s2u(const void* p) {
    uint32_t a;
    asm("{ .reg .u64 t; cvta.to.shared.u64 t, %1; cvt.u32.u64 %0, t; }" : "=r"(a) : "l"(p));
    return a;
}
__device__ __forceinline__ void ldm4(uint32_t* r, uint32_t a) {
    asm volatile("ldmatrix.sync.aligned.m8n8.x4.shared.b16 {%0,%1,%2,%3}, [%4];"
                 : "=r"(r[0]), "=r"(r[1]), "=r"(r[2]), "=r"(r[3]) : "r"(a));
}
__device__ __forceinline__ void ldm2(uint32_t* r, uint32_t a) {
    asm volatile("ldmatrix.sync.aligned.m8n8.x2.shared.b16 {%0,%1}, [%2];"
                 : "=r"(r[0]), "=r"(r[1]) : "r"(a));
}
__device__ __forceinline__ void ldm4t(uint32_t* r, uint32_t a) {
    asm volatile("ldmatrix.sync.aligned.m8n8.x4.trans.shared.b16 {%0,%1,%2,%3}, [%4];"
                 : "=r"(r[0]), "=r"(r[1]), "=r"(r[2]), "=r"(r[3]) : "r"(a));
}
__device__ __forceinline__ void mma16816(float* d, const uint32_t* a, const uint32_t* b) {
    asm volatile(
        "mma.sync.aligned.m16n8k16.row.col.f32.bf16.bf16.f32 "
        "{%0,%1,%2,%3}, {%4,%5,%6,%7}, {%8,%9}, {%0,%1,%2,%3};"
        : "+f"(d[0]), "+f"(d[1]), "+f"(d[2]), "+f"(d[3])
        : "r"(a[0]), "r"(a[1]), "r"(a[2]), "r"(a[3]), "r"(b[0]), "r"(b[1]));
}
// pack (e0 -> low half, e1 -> high half)
__device__ __forceinline__ uint32_t packbf(float e0, float e1) {
    uint32_t d;
    asm("cvt.rn.bf16x2.f32 %0, %1, %2;" : "=r"(d) : "f"(e1), "f"(e0));
    return d;
}
// split pair of floats into bf16 hi word + bf16 residual-lo word
__device__ __forceinline__ void split2(float f0, float f1, uint32_t& hi, uint32_t& lo) {
    hi = packbf(f0, f1);
    __nv_bfloat162 h = *reinterpret_cast<__nv_bfloat162*>(&hi);
    lo = packbf(f0 - __bfloat162float(h.x), f1 - __bfloat162float(h.y));
}
__device__ __forceinline__ void sts8B(uint32_t addr, uint32_t a, uint32_t b) {
    asm volatile("st.shared.v2.b32 [%0], {%1,%2};" :: "r"(addr), "r"(a), "r"(b));
}
__device__ __forceinline__ void sts16B(uint32_t addr, uint4 v) {
    asm volatile("st.shared.v4.b32 [%0], {%1,%2,%3,%4};"
                 :: "r"(addr), "r"(v.x), "r"(v.y), "r"(v.z), "r"(v.w));
}

// ---------------------------------------------------------------------------
// Fused QKV projection, bf16x3 split precision via mma.sync.
// CTA = 128 rows of X, all three matrices. 256 threads = 8 warps x 16 rows.
// K = 1024 in 16 chunks of 64.  (unchanged from R6)
// ---------------------------------------------------------------------------
#define PROJ_SMEM (2 * 128 * ST + 2 * 3 * 64 * ST)

__global__ __launch_bounds__(256) void proj_kernel(
    const float* __restrict__ x,
    const float* __restrict__ Wq, const float* __restrict__ bq,
    const float* __restrict__ Wk, const float* __restrict__ bk,
    const float* __restrict__ Wv, const float* __restrict__ bv)
{
    extern __shared__ __align__(16) uint8_t sm[];
    const uint32_t XHI = s2u(sm);
    const uint32_t XLO = XHI + 128 * ST;
    const uint32_t WHI = XLO + 128 * ST;
    const uint32_t WLO = WHI + 3 * 64 * ST;

    const int tid  = threadIdx.x;
    const int lane = tid & 31;
    const int warp = tid >> 5;
    const int wr   = warp * 16;
    const int m0   = blockIdx.x * 128;

    const float* Wm[3] = { Wq, Wk, Wv };

    float acc[3][8][4];
    #pragma unroll
    for (int m = 0; m < 3; m++)
        #pragma unroll
        for (int j = 0; j < 8; j++)
            #pragma unroll
            for (int e = 0; e < 4; e++) acc[m][j][e] = 0.0f;

    for (int c = 0; c < 16; c++) {
        const int k0 = c * 64;
        #pragma unroll
        for (int i = 0; i < 8; i++) {
            int idx = tid + i * 256;
            int row = idx >> 4, cg = idx & 15;
            float4 v = *(const float4*)&x[(size_t)(m0 + row) * D_MODEL + k0 + cg * 4];
            uint32_t h0, l0, h1, l1;
            split2(v.x, v.y, h0, l0);
            split2(v.z, v.w, h1, l1);
            uint32_t off = (uint32_t)(row * ST + cg * 8);
            sts8B(XHI + off, h0, h1);
            sts8B(XLO + off, l0, l1);
        }
        #pragma unroll
        for (int m = 0; m < 3; m++) {
            #pragma unroll
            for (int i = 0; i < 4; i++) {
                int idx = tid + i * 256;
                int row = idx >> 4, cg = idx & 15;
                float4 v = *(const float4*)&Wm[m][(size_t)(k0 + row) * D_HEAD + cg * 4];
                uint32_t h0, l0, h1, l1;
                split2(v.x, v.y, h0, l0);
                split2(v.z, v.w, h1, l1);
                uint32_t off = (uint32_t)(m * 64 * ST + row * ST + cg * 8);
                sts8B(WHI + off, h0, h1);
                sts8B(WLO + off, l0, l1);
            }
        }
        __syncthreads();

        #pragma unroll
        for (int t = 0; t < 3; t++) {
            const uint32_t abase = (t == 2) ? XLO : XHI;
            const uint32_t bsel  = (t == 1) ? WLO : WHI;
            #pragma unroll
            for (int ks = 0; ks < 4; ks++) {
                uint32_t a[4];
                ldm4(a, abase + (uint32_t)((wr + (lane & 15)) * ST + ks * 32 + (lane >> 4) * 16));
                #pragma unroll
                for (int m = 0; m < 3; m++) {
                    const uint32_t bbase = bsel + (uint32_t)(m * 64 * ST);
                    #pragma unroll
                    for (int nt = 0; nt < 4; nt++) {
                        uint32_t bf[4];
                        ldm4t(bf, bbase + (uint32_t)((ks * 16 + (lane & 15)) * ST + nt * 32 + (lane >> 4) * 16));
                        mma16816(acc[m][2 * nt],     a, bf + 0);
                        mma16816(acc[m][2 * nt + 1], a, bf + 2);
                    }
                }
            }
        }
        __syncthreads();
    }

    // ---- epilogue ----
    const int r0g = m0 + wr + (lane >> 2);
    const int r1g = r0g + 8;
    const int bb  = r0g >> 12;

    {   // Q
        float nsq0 = 0.0f, nsq1 = 0.0f;
        #pragma unroll
        for (int j = 0; j < 8; j++) {
            int h = j * 8 + 2 * (lane & 3);
            float b0 = __ldg(&bq[h]), b1 = __ldg(&bq[h + 1]);
            float v00 = (acc[0][j][0] + b0) * 0.125f, v01 = (acc[0][j][1] + b1) * 0.125f;
            float v10 = (acc[0][j][2] + b0) * 0.125f, v11 = (acc[0][j][3] + b1) * 0.125f;
            uint32_t hi, lo;
            split2(v00, v01, hi, lo);
            {
                __nv_bfloat162 H = *reinterpret_cast<__nv_bfloat162*>(&hi);
                __nv_bfloat162 L = *reinterpret_cast<__nv_bfloat162*>(&lo);
                float a0 = __bfloat162float(H.x) + __bfloat162float(L.x);
                float a1 = __bfloat162float(H.y) + __bfloat162float(L.y);
                nsq0 += a0 * a0 + a1 * a1;
            }
            g_Qhi[(size_t)r0g * 32 + h / 2] = hi;
            g_Qlo[(size_t)r0g * 32 + h / 2] = lo;
            split2(v10, v11, hi, lo);
            {
                __nv_bfloat162 H = *reinterpret_cast<__nv_bfloat162*>(&hi);
                __nv_bfloat162 L = *reinterpret_cast<__nv_bfloat162*>(&lo);
                float a0 = __bfloat162float(H.x) + __bfloat162float(L.x);
                float a1 = __bfloat162float(H.y) + __bfloat162float(L.y);
                nsq1 += a0 * a0 + a1 * a1;
            }
            g_Qhi[(size_t)r1g * 32 + h / 2] = hi;
            g_Qlo[(size_t)r1g * 32 + h / 2] = lo;
        }
        nsq0 += __shfl_xor_sync(0xffffffffu, nsq0, 1);
        nsq0 += __shfl_xor_sync(0xffffffffu, nsq0, 2);
        nsq1 += __shfl_xor_sync(0xffffffffu, nsq1, 1);
        nsq1 += __shfl_xor_sync(0xffffffffu, nsq1, 2);
        if ((lane & 3) == 0) {
            g_Qn[r0g] = sqrtf(nsq0);
            g_Qn[r1g] = sqrtf(nsq1);
        }
    }
    {   // K
        float nsq0 = 0.0f, nsq1 = 0.0f;
        #pragma unroll
        for (int j = 0; j < 8; j++) {
            int h = j * 8 + 2 * (lane & 3);
            float b0 = __ldg(&bk[h]), b1 = __ldg(&bk[h + 1]);
            float v00 = acc[1][j][0] + b0, v01 = acc[1][j][1] + b1;
            float v10 = acc[1][j][2] + b0, v11 = acc[1][j][3] + b1;
            uint32_t hi, lo;
            split2(v00, v01, hi, lo);
            {
                __nv_bfloat162 H = *reinterpret_cast<__nv_bfloat162*>(&hi);
                __nv_bfloat162 L = *reinterpret_cast<__nv_bfloat162*>(&lo);
                float a0 = __bfloat162float(H.x) + __bfloat162float(L.x);
                float a1 = __bfloat162float(H.y) + __bfloat162float(L.y);
                nsq0 += a0 * a0 + a1 * a1;
            }
            g_Khi[(size_t)r0g * 32 + h / 2] = hi;
            g_Klo[(size_t)r0g * 32 + h / 2] = lo;
            split2(v10, v11, hi, lo);
            {
                __nv_bfloat162 H = *reinterpret_cast<__nv_bfloat162*>(&hi);
                __nv_bfloat162 L = *reinterpret_cast<__nv_bfloat162*>(&lo);
                float a0 = __bfloat162float(H.x) + __bfloat162float(L.x);
                float a1 = __bfloat162float(H.y) + __bfloat162float(L.y);
                nsq1 += a0 * a0 + a1 * a1;
            }
            g_Khi[(size_t)r1g * 32 + h / 2] = hi;
            g_Klo[(size_t)r1g * 32 + h / 2] = lo;
        }
        nsq0 += __shfl_xor_sync(0xffffffffu, nsq0, 1);
        nsq0 += __shfl_xor_sync(0xffffffffu, nsq0, 2);
        nsq1 += __shfl_xor_sync(0xffffffffu, nsq1, 1);
        nsq1 += __shfl_xor_sync(0xffffffffu, nsq1, 2);
        if ((lane & 3) == 0) {
            float mx = fmaxf(sqrtf(nsq0), sqrtf(nsq1));
            atomicMax(&g_Kmax[bb], __float_as_uint(mx));
        }
    }
    {   // V
        #pragma unroll
        for (int j = 0; j < 8; j++) {
            int h = j * 8 + 2 * (lane & 3);
            float b0 = __ldg(&bv[h]), b1 = __ldg(&bv[h + 1]);
            uint32_t hi, lo;
            split2(acc[2][j][0] + b0, acc[2][j][1] + b1, hi, lo);
            g_Vhi[(size_t)r0g * 32 + h / 2] = hi;
            g_Vlo[(size_t)r0g * 32 + h / 2] = lo;
            split2(acc[2][j][2] + b0, acc[2][j][3] + b1, hi, lo);
            g_Vhi[(size_t)r1g * 32 + h / 2] = hi;
            g_Vlo[(size_t)r1g * 32 + h / 2] = lo;
        }
    }
}

// ---------------------------------------------------------------------------
// Flash attention, bf16x3, bound-softmax, split-K 4-ways, 512 threads.
// CTA = 64 q rows of one batch, 16 warps:
//   wq = warp & 3  -> q rows wq*16..+15
//   wk = warp >> 2 -> key quarter (32 keys) of the 128-key tile
// Each warp accumulates partial O/l over its key quarter; 4-way cross-warp
// smem reduction at the end (overlaying the dead K/V region).
// smem: Qhi/Qlo [64 rows] + Khi/Klo/Vhi/Vlo [128 rows] + bnd[64]  (~92 KB)
// ---------------------------------------------------------------------------
#define ATTN_SMEM (2 * 64 * ST + 4 * 128 * ST + 64 * 4)

__global__ __launch_bounds__(512) void attn_kernel(float* __restrict__ out)
{
    extern __shared__ __align__(16) uint8_t sm[];
    const uint32_t QHI = s2u(sm);
    const uint32_t QLO = QHI + 64 * ST;
    const uint32_t KHI = QLO + 64 * ST;
    const uint32_t KLO = KHI + 128 * ST;
    const uint32_t VHI = KLO + 128 * ST;
    const uint32_t VLO = VHI + 128 * ST;
    float* BND = (float*)(sm + 2 * 64 * ST + 4 * 128 * ST);
    // end-of-loop reduction overlays (inside the dead K/V region)
    float* OV = (float*)(sm + 2 * 64 * ST);                     // [3][4][32][36]
    float* LV = (float*)(sm + 2 * 64 * ST + 3 * 4 * 32 * 36 * 4);

    const int tid  = threadIdx.x;
    const int lane = tid & 31;
    const int warp = tid >> 5;
    const int wq   = warp & 3;
    const int wk   = warp >> 2;          // 0..3 key quarter
    const int wr   = wq * 16;
    const int b    = blockIdx.y;
    const int qt   = (gridDim.x - 1) - blockIdx.x;   // heaviest first
    const int q0   = qt * 64;

    // ---- stage Q tile + bounds ----
    {
        int row = tid >> 3, cg = tid & 7;            // 512 chunks per array
        size_t g = (size_t)(b * SEQ + q0 + row) * 32 + cg * 4;
        sts16B(QHI + (uint32_t)(row * ST + cg * 16), *(const uint4*)&g_Qhi[g]);
        sts16B(QLO + (uint32_t)(row * ST + cg * 16), *(const uint4*)&g_Qlo[g]);
    }
    {
        float kmax = __uint_as_float(g_Kmax[b]);
        if (tid < 64) BND[tid] = g_Qn[b * SEQ + q0 + tid] * kmax + 1.0f;
    }
    __syncthreads();

    float o[8][4];
    #pragma unroll
    for (int j = 0; j < 8; j++)
        #pragma unroll
        for (int e = 0; e < 4; e++) o[j][e] = 0.0f;
    float lsum0 = 0.0f, lsum1 = 0.0f;

    const float bnd0 = BND[wr + (lane >> 2)];
    const float bnd1 = BND[wr + (lane >> 2) + 8];
    const int   qg0  = q0 + wr + (lane >> 2);
    const int   qg1  = qg0 + 8;
    const int   qmxw = q0 + wr + 15;                 // max q row of this warp

    const int n_tiles = (q0 + 64 + 127) >> 7;        // 128-key tiles

    for (int kb = 0; kb < n_tiles; kb++) {
        // ---- stage K/V tiles (128 rows x 4 arrays, 512 threads) ----
        #pragma unroll
        for (int i = 0; i < 2; i++) {
            int idx = tid + i * 512;                 // 1024 16B chunks / array
            int row = idx >> 3, cg = idx & 7;
            size_t g = (size_t)(b * SEQ + kb * 128 + row) * 32 + cg * 4;
            uint32_t off = (uint32_t)(row * ST + cg * 16);
            sts16B(KHI + off, *(const uint4*)&g_Khi[g]);
            sts16B(KLO + off, *(const uint4*)&g_Klo[g]);
            sts16B(VHI + off, *(const uint4*)&g_Vhi[g]);
            sts16B(VLO + off, *(const uint4*)&g_Vlo[g]);
        }
        __syncthreads();

        const int keybase = kb * 128 + wk * 32;
        if (keybase <= qmxw) {
            // ---- S = Q K^T over this warp's 32-key quarter (3 split terms) ----
            float s[4][4];
            #pragma unroll
            for (int j = 0; j < 4; j++)
                #pragma unroll
                for (int e = 0; e < 4; e++) s[j][e] = 0.0f;

            #pragma unroll
            for (int t = 0; t < 3; t++) {
                const uint32_t abase = (t == 2) ? QLO : QHI;
                const uint32_t bbase = (t == 1) ? KLO : KHI;
                #pragma unroll
                for (int ks = 0; ks < 4; ks++) {
                    uint32_t a[4];
                    ldm4(a, abase + (uint32_t)((wr + (lane & 15)) * ST + ks * 32 + (lane >> 4) * 16));
                    #pragma unroll
                    for (int nt = 0; nt < 2; nt++) {
                        uint32_t kf[4];
                        ldm4(kf, bbase + (uint32_t)((wk * 32 + nt * 16 + (lane & 15)) * ST + ks * 32 + (lane >> 4) * 16));
                        uint32_t b0[2] = { kf[0], kf[2] };
                        uint32_t b1[2] = { kf[1], kf[3] };
                        mma16816(s[2 * nt],     a, b0);
                        mma16816(s[2 * nt + 1], a, b1);
                    }
                }
            }

            // ---- softmax (fixed bound) + pack P to bf16 hi/lo A-frags ----
            uint32_t pah[2][4], pal[2][4];
            const bool diag = (kb == n_tiles - 1);
            #pragma unroll
            for (int j = 0; j < 4; j++) {
                int key = keybase + j * 8 + 2 * (lane & 3);
                float p00 = __expf(s[j][0] - bnd0);
                float p01 = __expf(s[j][1] - bnd0);
                float p10 = __expf(s[j][2] - bnd1);
                float p11 = __expf(s[j][3] - bnd1);
                if (diag) {
                    if (key     > qg0) p00 = 0.0f;
                    if (key + 1 > qg0) p01 = 0.0f;
                    if (key     > qg1) p10 = 0.0f;
                    if (key + 1 > qg1) p11 = 0.0f;
                }
                lsum0 += p00 + p01;
                lsum1 += p10 + p11;
                int ks = j >> 1, half = j & 1;
                uint32_t w0, w1, l0, l1;
                split2(p00, p01, w0, l0);
                split2(p10, p11, w1, l1);
                pah[ks][half * 2 + 0] = w0;
                pah[ks][half * 2 + 1] = w1;
                pal[ks][half * 2 + 0] = l0;
                pal[ks][half * 2 + 1] = l1;
            }

            // ---- O += P V over this warp's 32 V rows (3 split terms) ----
            #pragma unroll
            for (int t = 0; t < 3; t++) {
                uint32_t (*pa)[4] = (t == 1) ? pal : pah;
                const uint32_t vbase = (t == 2) ? VLO : VHI;
                #pragma unroll
                for (int ks = 0; ks < 2; ks++) {
                    #pragma unroll
                    for (int nt = 0; nt < 4; nt++) {
                        uint32_t vf[4];
                        ldm4t(vf, vbase + (uint32_t)((wk * 32 + ks * 16 + (lane & 15)) * ST + nt * 32 + (lane >> 4) * 16));
                        mma16816(o[2 * nt],     pa[ks], vf + 0);
                        mma16816(o[2 * nt + 1], pa[ks], vf + 2);
                    }
                }
            }
        }
        __syncthreads();
    }

    // ---- cross-warp reduction: wk=1..3 partials -> wk=0 ----
    if (wk > 0) {
        float* dst = OV + (size_t)(((wk - 1) * 4 + wq) * 32 + lane) * 36;
        #pragma unroll
        for (int j = 0; j < 8; j++)
            #pragma unroll
            for (int e = 0; e < 4; e++) dst[j * 4 + e] = o[j][e];
        LV[(((wk - 1) * 4 + wq) * 32 + lane) * 2 + 0] = lsum0;
        LV[(((wk - 1) * 4 + wq) * 32 + lane) * 2 + 1] = lsum1;
    }
    __syncthreads();
    if (wk == 0) {
        #pragma unroll
        for (int p = 0; p < 3; p++) {
            const float* src = OV + (size_t)((p * 4 + wq) * 32 + lane) * 36;
            #pragma unroll
            for (int j = 0; j < 8; j++)
                #pragma unroll
                for (int e = 0; e < 4; e++) o[j][e] += src[j * 4 + e];
            lsum0 += LV[((p * 4 + wq) * 32 + lane) * 2 + 0];
            lsum1 += LV[((p * 4 + wq) * 32 + lane) * 2 + 1];
        }

        lsum0 += __shfl_xor_sync(0xffffffffu, lsum0, 1);
        lsum0 += __shfl_xor_sync(0xffffffffu, lsum0, 2);
        lsum1 += __shfl_xor_sync(0xffffffffu, lsum1, 1);
        lsum1 += __shfl_xor_sync(0xffffffffu, lsum1, 2);
        const float inv0 = 1.0f / lsum0;
        const float inv1 = 1.0f / lsum1;
        const size_t row0 = (size_t)(b * SEQ + qg0);
        const size_t row1 = (size_t)(b * SEQ + qg1);
        #pragma unroll
        for (int j = 0; j < 8; j++) {
            int h = j * 8 + 2 * (lane & 3);
            float2 v0 = { o[j][0] * inv0, o[j][1] * inv0 };
            float2 v1 = { o[j][2] * inv1, o[j][3] * inv1 };
            *(float2*)&out[row0 * D_HEAD + h] = v0;
            *(float2*)&out[row1 * D_HEAD + h] = v1;
        }
    }
}

// ---------------------------------------------------------------------------
// Launch
// ---------------------------------------------------------------------------
extern "C" void kernel_launch(void* const* d_in, const int* in_sizes, int n_in,
                              void* d_out, int out_size)
{
    const float* x  = (const float*)d_in[0];
    const float* Wq = (const float*)d_in[1];
    const float* bq = (const float*)d_in[2];
    const float* Wk = (const float*)d_in[3];
    const float* bk = (const float*)d_in[4];
    const float* Wv = (const float*)d_in[5];
    const float* bv = (const float*)d_in[6];
    float* out = (float*)d_out;

    cudaFuncSetAttribute(proj_kernel, cudaFuncAttributeMaxDynamicSharedMemorySize, PROJ_SMEM);
    cudaFuncSetAttribute(attn_kernel, cudaFuncAttributeMaxDynamicSharedMemorySize, ATTN_SMEM);

    proj_kernel<<<M_TOTAL / 128, 256, PROJ_SMEM>>>(x, Wq, bq, Wk, bk, Wv, bv);
    attn_kernel<<<dim3(SEQ / 64, BATCH), 512, ATTN_SMEM>>>(out);
}

// round 8
// speedup vs baseline: 3.1372x; 1.0626x over previous
#include <cuda_runtime.h>
#include <cuda_bf16.h>
#include <math.h>
#include <stdint.h>

#define D_MODEL 1024
#define D_HEAD  64
#define BATCH   4
#define SEQ     4096
#define M_TOTAL (BATCH * SEQ)   // 16384

// smem tile row stride in bytes (72 bf16 = 144B)
#define ST 144

// ---------------------------------------------------------------------------
// Device-global scratch. Q/K/V packed bf16 pairs along head dim: [row][32 words].
// g_Wsp: W pre-split [mat*2+part][1024 rows(k)][32 words(h pairs)].
// ---------------------------------------------------------------------------
__device__ uint32_t g_Qhi[M_TOTAL * 32], g_Qlo[M_TOTAL * 32];
__device__ uint32_t g_Khi[M_TOTAL * 32], g_Klo[M_TOTAL * 32];
__device__ uint32_t g_Vhi[M_TOTAL * 32], g_Vlo[M_TOTAL * 32];
__device__ uint32_t g_Wsp[6 * 1024 * 32];
__device__ float    g_Qn[M_TOTAL];
__device__ unsigned g_Kmax[BATCH];

// ---------------------------------------------------------------------------
// PTX helpers (sm_80-era; valid at plain sm_100 target)
// ---------------------------------------------------------------------------
__device__ __forceinline__ uint32_t s2u(const void* p) {
    uint32_t a;
    asm("{ .reg .u64 t; cvta.to.shared.u64 t, %1; cvt.u32.u64 %0, t; }" : "=r"(a) : "l"(p));
    return a;
}
__device__ __forceinline__ void ldm4(uint32_t* r, uint32_t a) {
    asm volatile("ldmatrix.sync.aligned.m8n8.x4.shared.b16 {%0,%1,%2,%3}, [%4];"
                 : "=r"(r[0]), "=r"(r[1]), "=r"(r[2]), "=r"(r[3]) : "r"(a));
}
__device__ __forceinline__ void ldm4t(uint32_t* r, uint32_t a) {
    asm volatile("ldmatrix.sync.aligned.m8n8.x4.trans.shared.b16 {%0,%1,%2,%3}, [%4];"
                 : "=r"(r[0]), "=r"(r[1]), "=r"(r[2]), "=r"(r[3]) : "r"(a));
}
__device__ __forceinline__ void mma16816(float* d, const uint32_t* a, const uint32_t* b) {
    asm volatile(
        "mma.sync.aligned.m16n8k16.row.col.f32.bf16.bf16.f32 "
        "{%0,%1,%2,%3}, {%4,%5,%6,%7}, {%8,%9}, {%0,%1,%2,%3};"
        : "+f"(d[0]), "+f"(d[1]), "+f"(d[2]), "+f"(d[3])
        : "r"(a[0]), "r"(a[1]), "r"(a[2]), "r"(a[3]), "r"(b[0]), "r"(b[1]));
}
__device__ __forceinline__ uint32_t packbf(float e0, float e1) {
    uint32_t d;
    asm("cvt.rn.bf16x2.f32 %0, %1, %2;" : "=r"(d) : "f"(e1), "f"(e0));
    return d;
}
__device__ __forceinline__ void split2(float f0, float f1, uint32_t& hi, uint32_t& lo) {
    hi = packbf(f0, f1);
    __nv_bfloat162 h = *reinterpret_cast<__nv_bfloat162*>(&hi);
    lo = packbf(f0 - __bfloat162float(h.x), f1 - __bfloat162float(h.y));
}
__device__ __forceinline__ void sts8B(uint32_t addr, uint32_t a, uint32_t b) {
    asm volatile("st.shared.v2.b32 [%0], {%1,%2};" :: "r"(addr), "r"(a), "r"(b));
}
__device__ __forceinline__ void sts16B(uint32_t addr, uint4 v) {
    asm volatile("st.shared.v4.b32 [%0], {%1,%2,%3,%4};"
                 :: "r"(addr), "r"(v.x), "r"(v.y), "r"(v.z), "r"(v.w));
}
__device__ __forceinline__ void cpa16(uint32_t s, const void* g) {
    asm volatile("cp.async.cg.shared.global [%0], [%1], 16;" :: "r"(s), "l"(g));
}
#define CP_COMMIT() asm volatile("cp.async.commit_group;" ::: "memory")
#define CP_WAIT1()  asm volatile("cp.async.wait_group 1;" ::: "memory")
#define CP_WAIT0()  asm volatile("cp.async.wait_group 0;" ::: "memory")

// ---------------------------------------------------------------------------
// W pre-split: g_Wsp[mat*2+part][k][w]  (bf16 hi/lo pairs of W^ [k][2w,2w+1])
// ---------------------------------------------------------------------------
__global__ void wsplit_kernel(const float* __restrict__ Wq,
                              const float* __restrict__ Wk,
                              const float* __restrict__ Wv) {
    int idx = blockIdx.x * blockDim.x + threadIdx.x;   // 3*1024*32 total
    if (idx >= 3 * 1024 * 32) return;
    int mat = idx >> 15;
    int r   = idx & 32767;
    int k   = r >> 5;
    int w   = r & 31;
    const float* W = (mat == 0) ? Wq : (mat == 1) ? Wk : Wv;
    float f0 = W[(size_t)k * D_HEAD + 2 * w];
    float f1 = W[(size_t)k * D_HEAD + 2 * w + 1];
    uint32_t hi, lo;
    split2(f0, f1, hi, lo);
    g_Wsp[(size_t)(mat * 2 + 0) * 32768 + k * 32 + w] = hi;
    g_Wsp[(size_t)(mat * 2 + 1) * 32768 + k * 32 + w] = lo;
}

// ---------------------------------------------------------------------------
// Fused QKV projection, bf16x3 via mma.sync, operand-grouped.
// CTA = 128 rows, 256 threads = 8 warps x 16 rows. K = 1024 in 16 chunks.
// W staged via cp.async from pre-split g_Wsp; X split on the fly (overlaps W).
// ---------------------------------------------------------------------------
#define PROJ_SMEM (2 * 128 * ST + 6 * 64 * ST)

__global__ __launch_bounds__(256) void proj_kernel(
    const float* __restrict__ x,
    const float* __restrict__ bq, const float* __restrict__ bk,
    const float* __restrict__ bv)
{
    extern __shared__ __align__(16) uint8_t sm[];
    const uint32_t XHI = s2u(sm);
    const uint32_t XLO = XHI + 128 * ST;
    const uint32_t WT  = XLO + 128 * ST;   // 6 tiles of 64*ST: [mat*2+part]

    const int tid  = threadIdx.x;
    const int lane = tid & 31;
    const int warp = tid >> 5;
    const int wr   = warp * 16;
    const int m0   = blockIdx.x * 128;

    float acc[3][8][4];
    #pragma unroll
    for (int m = 0; m < 3; m++)
        #pragma unroll
        for (int j = 0; j < 8; j++)
            #pragma unroll
            for (int e = 0; e < 4; e++) acc[m][j][e] = 0.0f;

    for (int c = 0; c < 16; c++) {
        const int k0 = c * 64;
        // ---- W tiles via cp.async (6 arrays x 64 rows x 8 cgs = 3072) ----
        #pragma unroll
        for (int i = 0; i < 12; i++) {
            int idx = tid + i * 256;
            int arr = idx >> 9;
            int r   = (idx >> 3) & 63;
            int cg  = idx & 7;
            cpa16(WT + (uint32_t)(arr * 64 * ST + r * ST + cg * 16),
                  g_Wsp + (size_t)arr * 32768 + (size_t)(k0 + r) * 32 + cg * 4);
        }
        CP_COMMIT();
        // ---- X chunk: LDG + split + STS (overlaps in-flight W cp.async) ----
        #pragma unroll
        for (int i = 0; i < 8; i++) {
            int idx = tid + i * 256;
            int row = idx >> 4, cg = idx & 15;
            float4 v = *(const float4*)&x[(size_t)(m0 + row) * D_MODEL + k0 + cg * 4];
            uint32_t h0, l0, h1, l1;
            split2(v.x, v.y, h0, l0);
            split2(v.z, v.w, h1, l1);
            uint32_t off = (uint32_t)(row * ST + cg * 8);
            sts8B(XHI + off, h0, h1);
            sts8B(XLO + off, l0, l1);
        }
        CP_WAIT0();
        __syncthreads();

        // ---- operand-grouped MMAs ----
        #pragma unroll
        for (int ks = 0; ks < 4; ks++) {
            uint32_t ah[4], al[4];
            ldm4(ah, XHI + (uint32_t)((wr + (lane & 15)) * ST + ks * 32 + (lane >> 4) * 16));
            ldm4(al, XLO + (uint32_t)((wr + (lane & 15)) * ST + ks * 32 + (lane >> 4) * 16));
            #pragma unroll
            for (int m = 0; m < 3; m++) {
                #pragma unroll
                for (int nt = 0; nt < 4; nt++) {
                    uint32_t wf[4];
                    const uint32_t roff = (uint32_t)((ks * 16 + (lane & 15)) * ST + nt * 32 + (lane >> 4) * 16);
                    ldm4t(wf, WT + (uint32_t)((2 * m) * 64 * ST) + roff);
                    mma16816(acc[m][2 * nt],     ah, wf + 0);
                    mma16816(acc[m][2 * nt + 1], ah, wf + 2);
                    mma16816(acc[m][2 * nt],     al, wf + 0);
                    mma16816(acc[m][2 * nt + 1], al, wf + 2);
                    ldm4t(wf, WT + (uint32_t)((2 * m + 1) * 64 * ST) + roff);
                    mma16816(acc[m][2 * nt],     ah, wf + 0);
                    mma16816(acc[m][2 * nt + 1], ah, wf + 2);
                }
            }
        }
        __syncthreads();
    }

    // ---- epilogue ----
    const int r0g = m0 + wr + (lane >> 2);
    const int r1g = r0g + 8;
    const int bb  = r0g >> 12;

    {   // Q
        float nsq0 = 0.0f, nsq1 = 0.0f;
        #pragma unroll
        for (int j = 0; j < 8; j++) {
            int h = j * 8 + 2 * (lane & 3);
            float b0 = __ldg(&bq[h]), b1 = __ldg(&bq[h + 1]);
            float v00 = (acc[0][j][0] + b0) * 0.125f, v01 = (acc[0][j][1] + b1) * 0.125f;
            float v10 = (acc[0][j][2] + b0) * 0.125f, v11 = (acc[0][j][3] + b1) * 0.125f;
            uint32_t hi, lo;
            split2(v00, v01, hi, lo);
            {
                __nv_bfloat162 H = *reinterpret_cast<__nv_bfloat162*>(&hi);
                __nv_bfloat162 L = *reinterpret_cast<__nv_bfloat162*>(&lo);
                float a0 = __bfloat162float(H.x) + __bfloat162float(L.x);
                float a1 = __bfloat162float(H.y) + __bfloat162float(L.y);
                nsq0 += a0 * a0 + a1 * a1;
            }
            g_Qhi[(size_t)r0g * 32 + h / 2] = hi;
            g_Qlo[(size_t)r0g * 32 + h / 2] = lo;
            split2(v10, v11, hi, lo);
            {
                __nv_bfloat162 H = *reinterpret_cast<__nv_bfloat162*>(&hi);
                __nv_bfloat162 L = *reinterpret_cast<__nv_bfloat162*>(&lo);
                float a0 = __bfloat162float(H.x) + __bfloat162float(L.x);
                float a1 = __bfloat162float(H.y) + __bfloat162float(L.y);
                nsq1 += a0 * a0 + a1 * a1;
            }
            g_Qhi[(size_t)r1g * 32 + h / 2] = hi;
            g_Qlo[(size_t)r1g * 32 + h / 2] = lo;
        }
        nsq0 += __shfl_xor_sync(0xffffffffu, nsq0, 1);
        nsq0 += __shfl_xor_sync(0xffffffffu, nsq0, 2);
        nsq1 += __shfl_xor_sync(0xffffffffu, nsq1, 1);
        nsq1 += __shfl_xor_sync(0xffffffffu, nsq1, 2);
        if ((lane & 3) == 0) {
            g_Qn[r0g] = sqrtf(nsq0);
            g_Qn[r1g] = sqrtf(nsq1);
        }
    }
    {   // K
        float nsq0 = 0.0f, nsq1 = 0.0f;
        #pragma unroll
        for (int j = 0; j < 8; j++) {
            int h = j * 8 + 2 * (lane & 3);
            float b0 = __ldg(&bk[h]), b1 = __ldg(&bk[h + 1]);
            float v00 = acc[1][j][0] + b0, v01 = acc[1][j][1] + b1;
            float v10 = acc[1][j][2] + b0, v11 = acc[1][j][3] + b1;
            uint32_t hi, lo;
            split2(v00, v01, hi, lo);
            {
                __nv_bfloat162 H = *reinterpret_cast<__nv_bfloat162*>(&hi);
                __nv_bfloat162 L = *reinterpret_cast<__nv_bfloat162*>(&lo);
                float a0 = __bfloat162float(H.x) + __bfloat162float(L.x);
                float a1 = __bfloat162float(H.y) + __bfloat162float(L.y);
                nsq0 += a0 * a0 + a1 * a1;
            }
            g_Khi[(size_t)r0g * 32 + h / 2] = hi;
            g_Klo[(size_t)r0g * 32 + h / 2] = lo;
            split2(v10, v11, hi, lo);
            {
                __nv_bfloat162 H = *reinterpret_cast<__nv_bfloat162*>(&hi);
                __nv_bfloat162 L = *reinterpret_cast<__nv_bfloat162*>(&lo);
                float a0 = __bfloat162float(H.x) + __bfloat162float(L.x);
                float a1 = __bfloat162float(H.y) + __bfloat162float(L.y);
                nsq1 += a0 * a0 + a1 * a1;
            }
            g_Khi[(size_t)r1g * 32 + h / 2] = hi;
            g_Klo[(size_t)r1g * 32 + h / 2] = lo;
        }
        nsq0 += __shfl_xor_sync(0xffffffffu, nsq0, 1);
        nsq0 += __shfl_xor_sync(0xffffffffu, nsq0, 2);
        nsq1 += __shfl_xor_sync(0xffffffffu, nsq1, 1);
        nsq1 += __shfl_xor_sync(0xffffffffu, nsq1, 2);
        if ((lane & 3) == 0) {
            float mx = fmaxf(sqrtf(nsq0), sqrtf(nsq1));
            atomicMax(&g_Kmax[bb], __float_as_uint(mx));
        }
    }
    {   // V
        #pragma unroll
        for (int j = 0; j < 8; j++) {
            int h = j * 8 + 2 * (lane & 3);
            float b0 = __ldg(&bv[h]), b1 = __ldg(&bv[h + 1]);
            uint32_t hi, lo;
            split2(acc[2][j][0] + b0, acc[2][j][1] + b1, hi, lo);
            g_Vhi[(size_t)r0g * 32 + h / 2] = hi;
            g_Vlo[(size_t)r0g * 32 + h / 2] = lo;
            split2(acc[2][j][2] + b0, acc[2][j][3] + b1, hi, lo);
            g_Vhi[(size_t)r1g * 32 + h / 2] = hi;
            g_Vlo[(size_t)r1g * 32 + h / 2] = lo;
        }
    }
}

// ---------------------------------------------------------------------------
// Flash attention, bf16x3, bound-softmax, split-K 4-ways, 512 threads,
// cp.async double-buffered K/V, operand-grouped MMAs.
// CTA = 64 q rows, 16 warps: wq = warp&3 (q slice), wk = warp>>2 (key quarter).
// smem: Q 2x64xST + 2 stages x (Khi,Klo,Vhi,Vlo)[128xST] + bnd  (~166 KB)
// ---------------------------------------------------------------------------
#define KVSTAGE (4 * 128 * ST)
#define ATTN_SMEM (2 * 64 * ST + 2 * KVSTAGE + 64 * 4)

__device__ __forceinline__ void stage_kv(uint32_t SB, int b, int kb, int tid) {
    #pragma unroll
    for (int i = 0; i < 2; i++) {
        int idx = tid + i * 512;
        int row = idx >> 3, cg = idx & 7;
        size_t g = (size_t)(b * SEQ + kb * 128 + row) * 32 + cg * 4;
        uint32_t off = (uint32_t)(row * ST + cg * 16);
        cpa16(SB + off,                g_Khi + g);
        cpa16(SB + 128 * ST + off,     g_Klo + g);
        cpa16(SB + 2 * 128 * ST + off, g_Vhi + g);
        cpa16(SB + 3 * 128 * ST + off, g_Vlo + g);
    }
}

__global__ __launch_bounds__(512) void attn_kernel(float* __restrict__ out)
{
    extern __shared__ __align__(16) uint8_t sm[];
    const uint32_t QHI = s2u(sm);
    const uint32_t QLO = QHI + 64 * ST;
    const uint32_t KV  = QLO + 64 * ST;              // stage s at KV + s*KVSTAGE
    float* BND = (float*)(sm + 2 * 64 * ST + 2 * KVSTAGE);
    // end-of-loop reduction overlays (dead stage region)
    float* OV = (float*)(sm + 2 * 64 * ST);          // [3][4][32][36]
    float* LV = (float*)(sm + 2 * 64 * ST + 3 * 4 * 32 * 36 * 4);

    const int tid  = threadIdx.x;
    const int lane = tid & 31;
    const int warp = tid >> 5;
    const int wq   = warp & 3;
    const int wk   = warp >> 2;
    const int wr   = wq * 16;
    const int b    = blockIdx.y;
    const int qt   = (gridDim.x - 1) - blockIdx.x;   // heaviest first
    const int q0   = qt * 64;

    const int n_tiles = (q0 + 64 + 127) >> 7;        // 128-key tiles

    // ---- prefetch tile 0 ----
    stage_kv(KV, b, 0, tid);
    CP_COMMIT();

    // ---- stage Q tile + bounds ----
    {
        int row = tid >> 3, cg = tid & 7;
        size_t g = (size_t)(b * SEQ + q0 + row) * 32 + cg * 4;
        sts16B(QHI + (uint32_t)(row * ST + cg * 16), *(const uint4*)&g_Qhi[g]);
        sts16B(QLO + (uint32_t)(row * ST + cg * 16), *(const uint4*)&g_Qlo[g]);
    }
    {
        float kmax = __uint_as_float(g_Kmax[b]);
        if (tid < 64) BND[tid] = g_Qn[b * SEQ + q0 + tid] * kmax + 1.0f;
    }
    __syncthreads();

    float o[8][4];
    #pragma unroll
    for (int j = 0; j < 8; j++)
        #pragma unroll
        for (int e = 0; e < 4; e++) o[j][e] = 0.0f;
    float lsum0 = 0.0f, lsum1 = 0.0f;

    const float bnd0 = BND[wr + (lane >> 2)];
    const float bnd1 = BND[wr + (lane >> 2) + 8];
    const int   qg0  = q0 + wr + (lane >> 2);
    const int   qg1  = qg0 + 8;
    const int   qmxw = q0 + wr + 15;

    const uint32_t qrow_off = (uint32_t)((wr + (lane & 15)) * ST + (lane >> 4) * 16);

    for (int kb = 0; kb < n_tiles; kb++) {
        if (kb + 1 < n_tiles) stage_kv(KV + (uint32_t)(((kb + 1) & 1) * KVSTAGE), b, kb + 1, tid);
        CP_COMMIT();
        CP_WAIT1();
        __syncthreads();

        const uint32_t SB   = KV + (uint32_t)((kb & 1) * KVSTAGE);
        const uint32_t KHIb = SB;
        const uint32_t KLOb = SB + 128 * ST;
        const uint32_t VHIb = SB + 2 * 128 * ST;
        const uint32_t VLOb = SB + 3 * 128 * ST;

        const int keybase = kb * 128 + wk * 32;
        if (keybase <= qmxw) {
            // ---- S = Q K^T, operand-grouped (Khi serves hi*hi and lo*hi) ----
            float s[4][4];
            #pragma unroll
            for (int j = 0; j < 4; j++)
                #pragma unroll
                for (int e = 0; e < 4; e++) s[j][e] = 0.0f;

            #pragma unroll
            for (int ks = 0; ks < 4; ks++) {
                uint32_t qh[4], ql[4];
                ldm4(qh, QHI + qrow_off + (uint32_t)(ks * 32));
                ldm4(ql, QLO + qrow_off + (uint32_t)(ks * 32));
                #pragma unroll
                for (int nt = 0; nt < 2; nt++) {
                    const uint32_t koff = (uint32_t)((wk * 32 + nt * 16 + (lane & 15)) * ST + ks * 32 + (lane >> 4) * 16);
                    uint32_t kf[4];
                    ldm4(kf, KHIb + koff);
                    {
                        uint32_t b0[2] = { kf[0], kf[2] };
                        uint32_t b1[2] = { kf[1], kf[3] };
                        mma16816(s[2 * nt],     qh, b0);
                        mma16816(s[2 * nt + 1], qh, b1);
                        mma16816(s[2 * nt],     ql, b0);
                        mma16816(s[2 * nt + 1], ql, b1);
                    }
                    ldm4(kf, KLOb + koff);
                    {
                        uint32_t b0[2] = { kf[0], kf[2] };
                        uint32_t b1[2] = { kf[1], kf[3] };
                        mma16816(s[2 * nt],     qh, b0);
                        mma16816(s[2 * nt + 1], qh, b1);
                    }
                }
            }

            // ---- softmax (fixed bound) + pack P to bf16 hi/lo A-frags ----
            uint32_t pah[2][4], pal[2][4];
            const bool diag = (kb == n_tiles - 1);
            #pragma unroll
            for (int j = 0; j < 4; j++) {
                int key = keybase + j * 8 + 2 * (lane & 3);
                float p00 = __expf(s[j][0] - bnd0);
                float p01 = __expf(s[j][1] - bnd0);
                float p10 = __expf(s[j][2] - bnd1);
                float p11 = __expf(s[j][3] - bnd1);
                if (diag) {
                    if (key     > qg0) p00 = 0.0f;
                    if (key + 1 > qg0) p01 = 0.0f;
                    if (key     > qg1) p10 = 0.0f;
                    if (key + 1 > qg1) p11 = 0.0f;
                }
                lsum0 += p00 + p01;
                lsum1 += p10 + p11;
                int ks = j >> 1, half = j & 1;
                uint32_t w0, w1, l0, l1;
                split2(p00, p01, w0, l0);
                split2(p10, p11, w1, l1);
                pah[ks][half * 2 + 0] = w0;
                pah[ks][half * 2 + 1] = w1;
                pal[ks][half * 2 + 0] = l0;
                pal[ks][half * 2 + 1] = l1;
            }

            // ---- O += P V, operand-grouped (Vhi serves Phi and Plo) ----
            #pragma unroll
            for (int ks = 0; ks < 2; ks++) {
                #pragma unroll
                for (int nt = 0; nt < 4; nt++) {
                    const uint32_t voff = (uint32_t)((wk * 32 + ks * 16 + (lane & 15)) * ST + nt * 32 + (lane >> 4) * 16);
                    uint32_t vf[4];
                    ldm4t(vf, VHIb + voff);
                    mma16816(o[2 * nt],     pah[ks], vf + 0);
                    mma16816(o[2 * nt + 1], pah[ks], vf + 2);
                    mma16816(o[2 * nt],     pal[ks], vf + 0);
                    mma16816(o[2 * nt + 1], pal[ks], vf + 2);
                    ldm4t(vf, VLOb + voff);
                    mma16816(o[2 * nt],     pah[ks], vf + 0);
                    mma16816(o[2 * nt + 1], pah[ks], vf + 2);
                }
            }
        }
        __syncthreads();
    }

    // ---- cross-warp reduction: wk=1..3 partials -> wk=0 ----
    if (wk > 0) {
        float* dst = OV + (size_t)(((wk - 1) * 4 + wq) * 32 + lane) * 36;
        #pragma unroll
        for (int j = 0; j < 8; j++)
            #pragma unroll
            for (int e = 0; e < 4; e++) dst[j * 4 + e] = o[j][e];
        LV[(((wk - 1) * 4 + wq) * 32 + lane) * 2 + 0] = lsum0;
        LV[(((wk - 1) * 4 + wq) * 32 + lane) * 2 + 1] = lsum1;
    }
    __syncthreads();
    if (wk == 0) {
        #pragma unroll
        for (int p = 0; p < 3; p++) {
            const float* src = OV + (size_t)((p * 4 + wq) * 32 + lane) * 36;
            #pragma unroll
            for (int j = 0; j < 8; j++)
                #pragma unroll
                for (int e = 0; e < 4; e++) o[j][e] += src[j * 4 + e];
            lsum0 += LV[((p * 4 + wq) * 32 + lane) * 2 + 0];
            lsum1 += LV[((p * 4 + wq) * 32 + lane) * 2 + 1];
        }

        lsum0 += __shfl_xor_sync(0xffffffffu, lsum0, 1);
        lsum0 += __shfl_xor_sync(0xffffffffu, lsum0, 2);
        lsum1 += __shfl_xor_sync(0xffffffffu, lsum1, 1);
        lsum1 += __shfl_xor_sync(0xffffffffu, lsum1, 2);
        const float inv0 = 1.0f / lsum0;
        const float inv1 = 1.0f / lsum1;
        const size_t row0 = (size_t)(b * SEQ + qg0);
        const size_t row1 = (size_t)(b * SEQ + qg1);
        #pragma unroll
        for (int j = 0; j < 8; j++) {
            int h = j * 8 + 2 * (lane & 3);
            float2 v0 = { o[j][0] * inv0, o[j][1] * inv0 };
            float2 v1 = { o[j][2] * inv1, o[j][3] * inv1 };
            *(float2*)&out[row0 * D_HEAD + h] = v0;
            *(float2*)&out[row1 * D_HEAD + h] = v1;
        }
    }
}

// ---------------------------------------------------------------------------
// Launch
// ---------------------------------------------------------------------------
extern "C" void kernel_launch(void* const* d_in, const int* in_sizes, int n_in,
                              void* d_out, int out_size)
{
    const float* x  = (const float*)d_in[0];
    const float* Wq = (const float*)d_in[1];
    const float* bq = (const float*)d_in[2];
    const float* Wk = (const float*)d_in[3];
    const float* bk = (const float*)d_in[4];
    const float* Wv = (const float*)d_in[5];
    const float* bv = (const float*)d_in[6];
    float* out = (float*)d_out;

    cudaFuncSetAttribute(proj_kernel, cudaFuncAttributeMaxDynamicSharedMemorySize, PROJ_SMEM);
    cudaFuncSetAttribute(attn_kernel, cudaFuncAttributeMaxDynamicSharedMemorySize, ATTN_SMEM);

    wsplit_kernel<<<(3 * 1024 * 32 + 255) / 256, 256>>>(Wq, Wk, Wv);
    proj_kernel<<<M_TOTAL / 128, 256, PROJ_SMEM>>>(x, bq, bk, bv);
    attn_kernel<<<dim3(SEQ / 64, BATCH), 512, ATTN_SMEM>>>(out);
}